// round 13
// baseline (speedup 1.0000x reference)
#include <cuda_runtime.h>
#include <math.h>

#define BATCH  8
#define N0     4096
#define N1     2048
#define N2     1024
#define FIN    64
#define LATENT 32
#define DEGMAX 128

// ---- packed fp32x2 helpers (Blackwell FFMA2 — only reachable via PTX) ----
#define PACK2(out, v) \
    asm("mov.b64 %0, {%1, %1};" : "=l"(out) : "r"(__float_as_uint(v)))
#define FMA2(acc, a, b) \
    asm("fma.rn.f32x2 %0, %1, %2, %0;" : "+l"(acc) : "l"(a), "l"(b))
#define UNPACK2(lo, hi, in) \
    asm("mov.b64 {%0, %1}, %2;" : "=r"(lo), "=r"(hi) : "l"(in))

// ---- PDL: wait until predecessor grid's memory is visible ----
__device__ __forceinline__ void pdl_wait() {
    asm volatile("griddepcontrol.wait;" ::: "memory");
}

// ---------------- device scratch ----------------
__device__ int   g_deg[N0];
__device__ int2  g_edge[N0 * DEGMAX];

__device__ int   g_deg1[BATCH * N1];
__device__ int2  g_edge1[BATCH * N1 * DEGMAX];
__device__ int   g_deg01[BATCH * N0];
__device__ int2  g_edge01[BATCH * N0 * DEGMAX];

__device__ int   g_deg2a[BATCH * N2];                // latent: cols level-1, gate-scaled
__device__ int2  g_edge2a[BATCH * N2 * DEGMAX];
__device__ int   g_deg2[BATCH * N2];                 // dec0: cols level-2
__device__ int2  g_edge2[BATCH * N2 * DEGMAX];
__device__ int   g_deg12[BATCH * N1];                // dec1: all N1 rows, cols level-2
__device__ int2  g_edge12[BATCH * N1 * DEGMAX];

__device__ float g_xw[BATCH][N0 * 128];
__device__ float g_h [BATCH][N0 * 128];
__device__ float g_h1[BATCH][N1 * 96];
__device__ float g_z [BATCH][N2 * LATENT];
__device__ float g_d0[BATCH][N2 * 64];
__device__ float g_y [BATCH][N0];

__device__ int   g_gidx1[BATCH][N1];
__device__ int   g_ginv1[BATCH][N0];
__device__ float g_gate1[BATCH][N1];
__device__ int   g_gidx2[BATCH][N2];
__device__ int   g_lidx2[BATCH][N2];
__device__ int   g_ginv2[BATCH][N0];
__device__ int   g_linv2[BATCH][N1];
__device__ float g_gate2[BATCH][N2];

// ---- fused: dense A0 row -> smem ELL (+persist) + spmm over x (all batches) + y zero ----
__global__ __launch_bounds__(256)
void spmm0_build(const float* __restrict__ A0, const float* __restrict__ x,
                 float* __restrict__ xwB, float* __restrict__ yB)
{
    __shared__ int2 sedge[DEGMAX];
    __shared__ int scnt[8];
    __shared__ int soff[8];
    __shared__ int sdeg;

    int r = blockIdx.x;
    int tid = threadIdx.x, w = tid >> 5, lane = tid & 31;
    const float* arow = A0 + (long)r * N0;

    int c0base = w * 512;
    int cnt = 0;
    for (int cc = c0base + lane; cc < c0base + 512; cc += 32) {
        unsigned m = __ballot_sync(0xffffffffu, arow[cc] != 0.0f);
        cnt += __popc(m);
    }
    if (lane == 0) scnt[w] = cnt;
    __syncthreads();
    if (tid == 0) {
        int s = 0;
        for (int i = 0; i < 8; i++) { soff[i] = s; s += scnt[i]; }
        sdeg = s < DEGMAX ? s : DEGMAX;
    }
    __syncthreads();

    int pos = soff[w];
    for (int cc = c0base + lane; cc < c0base + 512; cc += 32) {
        float v = arow[cc];
        unsigned m = __ballot_sync(0xffffffffu, v != 0.0f);
        if (v != 0.0f) {
            int p2 = pos + __popc(m & ((1u << lane) - 1u));
            if (p2 < DEGMAX) { int2 e; e.x = cc; e.y = __float_as_int(v); sedge[p2] = e; }
        }
        pos += __popc(m);
    }
    __syncthreads();

    int deg = sdeg;
    for (int e = tid; e < deg; e += 256) g_edge[(long)r * DEGMAX + e] = sedge[e];
    if (tid == 0) g_deg[r] = deg;
    if (tid < BATCH) yB[(long)tid * N0 + r] = 0.0f;

    int c = tid & 63, grp = tid >> 6;
    for (int b = grp; b < BATCH; b += 4) {
        const float* X = x + (long)b * N0 * FIN;
        float acc = 0.0f;
#pragma unroll 4
        for (int e = 0; e < deg; e++) {
            int2 pk = sedge[e];
            acc += __int_as_float(pk.y) * __ldg(X + (long)pk.x * FIN + c);
        }
        xwB[(long)b * ((long)N0 * 128) + (long)r * 64 + c] = acc;
    }
}

// ------- sub-ELL row remap core (one warp per row, ballot compaction) -------
// gateB != null : value *= gateB[b*sGate + mappedCol]
// emitSrc != 0  : emit source-space column (mapping used only as keep-filter)
__device__ __forceinline__ void build_rowX(int b, int r,
    const int2* __restrict__ srcEdge, long seStride,
    const int* __restrict__ srcDeg, long sdStride,
    const int* __restrict__ rowMapB, long sMap,
    const int* __restrict__ invB, long sInv,
    const float* __restrict__ gateB, long sGate, int emitSrc,
    int2* __restrict__ dstEdge, int* __restrict__ dstDeg, int nrows)
{
    int lane = threadIdx.x & 31;
    int src = rowMapB ? rowMapB[(long)b * sMap + r] : r;
    const int2* ep = srcEdge + (long)b * seStride + (long)src * DEGMAX;
    int deg = srcDeg[(long)b * sdStride + src];
    const int* inv = invB + (long)b * sInv;
    const float* gate = gateB ? (gateB + (long)b * sGate) : nullptr;
    int2* op = dstEdge + ((long)b * nrows + r) * DEGMAX;
    int base = 0;
    for (int c0 = 0; c0 < deg; c0 += 32) {
        int e = c0 + lane;
        int mc = -1; int2 pk;
        if (e < deg) { pk = __ldg(ep + e); mc = __ldg(inv + pk.x); }
        unsigned m = __ballot_sync(0xffffffffu, mc >= 0);
        if (mc >= 0) {
            int pos = base + __popc(m & ((1u << lane) - 1u));
            int2 o;
            o.x = emitSrc ? pk.x : mc;
            float v = __int_as_float(pk.y);
            if (gate) v *= __ldg(gate + mc);
            o.y = __float_as_int(v);
            op[pos] = o;
        }
        base += __popc(m);
    }
    if (lane == 0) dstDeg[(long)b * nrows + r] = base;
}

// ------- dual sub-ELL build after pool1: edge1 (gathered rows) + edge01 (identity) ----
__global__ void build_sub2(const int2* __restrict__ edge0, const int* __restrict__ deg0,
                           const int* __restrict__ gidx1, const int* __restrict__ ginv1,
                           int2* __restrict__ edge1, int* __restrict__ deg1,
                           int2* __restrict__ edge01, int* __restrict__ deg01)
{
    pdl_wait();
    int b = blockIdx.y;
    int bx = blockIdx.x;
    if (bx < N1 / 8) {
        int r = bx * 8 + (threadIdx.x >> 5);
        build_rowX(b, r, edge0, 0, deg0, 0, gidx1, N1, ginv1, N0,
                   nullptr, 0, 0, edge1, deg1, N1);
    } else {
        int r = (bx - N1 / 8) * 8 + (threadIdx.x >> 5);
        build_rowX(b, r, edge0, 0, deg0, 0, nullptr, 0, ginv1, N0,
                   nullptr, 0, 0, edge01, deg01, N0);
    }
}

// ------- triple sub-ELL build after pool2: edge2a + edge2 + edge12 ----
__global__ void build2x(const int2* __restrict__ edge1, const int* __restrict__ deg1,
                        const int* __restrict__ lidx2, const int* __restrict__ linv2,
                        const float* __restrict__ gate2,
                        int2* __restrict__ edge2a, int* __restrict__ deg2a,
                        int2* __restrict__ edge2,  int* __restrict__ deg2,
                        int2* __restrict__ edge12, int* __restrict__ deg12)
{
    pdl_wait();
    int b = blockIdx.y;
    int bx = blockIdx.x;
    const long E1S = (long)N1 * DEGMAX;
    if (bx < N2 / 8) {
        // latent edges: rows level-2, cols level-1 (emitSrc), values * gate2[linv2[col]]
        int r = bx * 8 + (threadIdx.x >> 5);
        build_rowX(b, r, edge1, E1S, deg1, N1, lidx2, N2, linv2, N1,
                   gate2, N2, 1, edge2a, deg2a, N2);
    } else if (bx < 2 * (N2 / 8)) {
        // dec0 edges: standard level-2 adjacency
        int r = (bx - N2 / 8) * 8 + (threadIdx.x >> 5);
        build_rowX(b, r, edge1, E1S, deg1, N1, lidx2, N2, linv2, N1,
                   nullptr, 0, 0, edge2, deg2, N2);
    } else {
        // dec1 edges: all N1 rows, cols remapped to level-2 (unpool fold)
        int r = (bx - 2 * (N2 / 8)) * 8 + (threadIdx.x >> 5);
        build_rowX(b, r, edge1, E1S, deg1, N1, nullptr, 0, linv2, N1,
                   nullptr, 0, 0, edge12, deg12, N1);
    }
}

// ---------------- GEMM: 128x64 tile, 8x4 per thread, FFMA2 (batched) ----------
// MODE 0: plain  MODE 1: gather*scale
// EPI bit0: bias+relu ; bit1: fused y += relu_row . p
template<int K, int C, int MODE, int EPI>
__global__ __launch_bounds__(256)
void gemmT(const float* __restrict__ Ab, long sA,
           const float* __restrict__ W,
           const float* __restrict__ bias,
           float* __restrict__ Ob, long sO,
           const int* __restrict__ mapB, long sMap,
           const float* __restrict__ scaleB,
           const float* __restrict__ p, float* __restrict__ yB)
{
    __shared__ float As[32][128];
    __shared__ float Ws[32][64];

    int b = blockIdx.z;
    const float* A = Ab + (long)b * sA;
    float*       O = Ob + (long)b * sO;
    int tid = threadIdx.x;
    int rowTile = blockIdx.y * 128;
    int colTile = blockIdx.x * 64;

    int lr = tid >> 1;
    int lk = (tid & 1) * 16;
    int grow = rowTile + lr;
    int wr  = tid >> 3;
    int wc0 = (tid & 7) * 8;
    int ry = tid >> 4, rx = tid & 15;

    // pre-wait prologue: W is a read-only kernel input — preload k-tile 0
#pragma unroll
    for (int t = 0; t < 8; t += 4) {
        int cc = colTile + wc0 + t;
        float4 v = (cc < C) ? *(const float4*)(W + (long)wr * C + cc)
                            : make_float4(0.f, 0.f, 0.f, 0.f);
        *(float4*)&Ws[wr][wc0 + t] = v;
    }

    pdl_wait();

    const float* asrc = nullptr;
    float ascale = 1.0f;
    if (MODE == 0) {
        asrc = A + (long)grow * K;
    } else {
        int s = mapB[(long)b * sMap + grow];
        asrc = A + (long)s * K;
        ascale = scaleB[(long)b * sMap + grow];
    }

    unsigned long long accP[4][4];
#pragma unroll
    for (int i = 0; i < 4; i++)
#pragma unroll
        for (int j = 0; j < 4; j++) accP[i][j] = 0ull;

    for (int kt = 0; kt < K; kt += 32) {
#pragma unroll
        for (int t = 0; t < 16; t += 4) {
            float4 v = asrc ? *(const float4*)(asrc + kt + lk + t)
                            : make_float4(0.f, 0.f, 0.f, 0.f);
            As[lk + t + 0][lr] = v.x * ascale;
            As[lk + t + 1][lr] = v.y * ascale;
            As[lk + t + 2][lr] = v.z * ascale;
            As[lk + t + 3][lr] = v.w * ascale;
        }
        if (kt > 0) {
#pragma unroll
            for (int t = 0; t < 8; t += 4) {
                int cc = colTile + wc0 + t;
                float4 v = (cc < C) ? *(const float4*)(W + (long)(kt + wr) * C + cc)
                                    : make_float4(0.f, 0.f, 0.f, 0.f);
                *(float4*)&Ws[wr][wc0 + t] = v;
            }
        }
        __syncthreads();

#pragma unroll
        for (int kk = 0; kk < 32; kk++) {
            ulonglong2 a01 = *(const ulonglong2*)(&As[kk][ry * 8]);
            ulonglong2 a23 = *(const ulonglong2*)(&As[kk][ry * 8 + 4]);
            float4 wv = *(const float4*)(&Ws[kk][rx * 4]);
            unsigned long long w0, w1, w2, w3;
            PACK2(w0, wv.x); PACK2(w1, wv.y); PACK2(w2, wv.z); PACK2(w3, wv.w);

            FMA2(accP[0][0], a01.x, w0); FMA2(accP[0][1], a01.x, w1);
            FMA2(accP[0][2], a01.x, w2); FMA2(accP[0][3], a01.x, w3);
            FMA2(accP[1][0], a01.y, w0); FMA2(accP[1][1], a01.y, w1);
            FMA2(accP[1][2], a01.y, w2); FMA2(accP[1][3], a01.y, w3);
            FMA2(accP[2][0], a23.x, w0); FMA2(accP[2][1], a23.x, w1);
            FMA2(accP[2][2], a23.x, w2); FMA2(accP[2][3], a23.x, w3);
            FMA2(accP[3][0], a23.y, w0); FMA2(accP[3][1], a23.y, w1);
            FMA2(accP[3][2], a23.y, w2); FMA2(accP[3][3], a23.y, w3);
        }
        __syncthreads();
    }

    float acc[8][4];
#pragma unroll
    for (int i = 0; i < 4; i++)
#pragma unroll
        for (int j = 0; j < 4; j++) {
            unsigned lo, hi;
            UNPACK2(lo, hi, accP[i][j]);
            acc[2 * i][j]     = __uint_as_float(lo);
            acc[2 * i + 1][j] = __uint_as_float(hi);
        }

    int cc = colTile + rx * 4;
    if (cc < C) {
        if (EPI == 0) {
#pragma unroll
            for (int i = 0; i < 8; i++) {
                long r = rowTile + ry * 8 + i;
                *(float4*)(O + r * C + cc) =
                    make_float4(acc[i][0], acc[i][1], acc[i][2], acc[i][3]);
            }
        } else {
            float4 bv = *(const float4*)(bias + cc);
            float4 pv = make_float4(0.f, 0.f, 0.f, 0.f);
            if (EPI & 2) pv = *(const float4*)(p + cc);
            float part[8];
#pragma unroll
            for (int i = 0; i < 8; i++) {
                long r = rowTile + ry * 8 + i;
                float4 o;
                o.x = fmaxf(acc[i][0] + bv.x, 0.0f);
                o.y = fmaxf(acc[i][1] + bv.y, 0.0f);
                o.z = fmaxf(acc[i][2] + bv.z, 0.0f);
                o.w = fmaxf(acc[i][3] + bv.w, 0.0f);
                *(float4*)(O + r * C + cc) = o;
                part[i] = o.x * pv.x + o.y * pv.y + o.z * pv.z + o.w * pv.w;
            }
            if (EPI & 2) {
#pragma unroll
                for (int i = 0; i < 8; i++) {
                    float v = part[i];
#pragma unroll
                    for (int o = 8; o > 0; o >>= 1)
                        v += __shfl_down_sync(0xffffffffu, v, o, 16);
                    if ((tid & 15) == 0)
                        atomicAdd(&yB[(long)b * N0 + rowTile + ry * 8 + i], v);
                }
            }
        }
    }
}

// ---------------- fused GCN: u = A@X (smem) then O = u@W + b (row-local) ------
// ACT: 0 none, 1 relu.  REPARAM: emit z/mean/logvar instead of O.
// grid (1, nrows/128, BATCH), 256 threads, dynamic smem = (CIN*128 + CIN*COUT)*4
template<int CIN, int COUT, int ACT, int REPARAM>
__global__ __launch_bounds__(256)
void gcnF(const int2* __restrict__ edgeB, long eStride,
          const int*  __restrict__ degB,  long dStride,
          const float* __restrict__ Xb, long sX,
          const float* __restrict__ W,
          const float* __restrict__ bias,
          float* __restrict__ Ob, long sO,
          const float* __restrict__ epsB,
          float* __restrict__ meanOutB, float* __restrict__ lvOutB,
          float* __restrict__ zB)
{
    constexpr int NC  = COUT / 16;
    constexpr int RPI = 256 / CIN;
    extern __shared__ float sm[];
    float* U   = sm;                  // [CIN][128] k-major
    float* Wsm = sm + CIN * 128;      // [CIN][COUT]

    int b = blockIdx.z;
    int rowTile = blockIdx.y * 128;
    int tid = threadIdx.x;
    int rx = tid & 15, ry = tid >> 4;

    // pre-wait prologue: W and bias are read-only kernel inputs
    for (int i = tid; i < CIN * COUT; i += 256) Wsm[i] = __ldg(W + i);
    float bb[NC];
#pragma unroll
    for (int j = 0; j < NC; j++) bb[j] = __ldg(bias + rx * NC + j);

    pdl_wait();

    // ---- phase 1: SpMM rows rowTile..rowTile+127 into U (transposed) ----
    {
        const float* X = Xb + (long)b * sX;
        int c  = tid % CIN;
        int ty = tid / CIN;
        for (int rg = 0; rg < 128; rg += RPI) {
            int r = rowTile + rg + ty;
            int deg = degB[(long)b * dStride + r];
            const int2* ep = edgeB + (long)b * eStride + (long)r * DEGMAX;
            float acc = 0.0f;
#pragma unroll 4
            for (int e = 0; e < deg; e++) {
                int2 pk = __ldg(ep + e);
                acc += __int_as_float(pk.y) * __ldg(X + (long)pk.x * CIN + c);
            }
            U[c * 128 + rg + ty] = acc;
        }
    }
    __syncthreads();

    // ---- phase 2: GEMM from smem ----
    unsigned long long accP[4][NC];
#pragma unroll
    for (int i = 0; i < 4; i++)
#pragma unroll
        for (int j = 0; j < NC; j++) accP[i][j] = 0ull;

#pragma unroll 4
    for (int kk = 0; kk < CIN; kk++) {
        ulonglong2 a01 = *(const ulonglong2*)(U + kk * 128 + ry * 8);
        ulonglong2 a23 = *(const ulonglong2*)(U + kk * 128 + ry * 8 + 4);
        unsigned long long av[4] = {a01.x, a01.y, a23.x, a23.y};
        unsigned long long w[NC];
        if constexpr (NC == 4) {
            float4 wv = *(const float4*)(Wsm + kk * COUT + rx * 4);
            PACK2(w[0], wv.x); PACK2(w[1], wv.y); PACK2(w[2], wv.z); PACK2(w[3], wv.w);
        } else {
#pragma unroll
            for (int j = 0; j < NC; j++) PACK2(w[j], Wsm[kk * COUT + rx * NC + j]);
        }
#pragma unroll
        for (int i = 0; i < 4; i++)
#pragma unroll
            for (int j = 0; j < NC; j++) FMA2(accP[i][j], av[i], w[j]);
    }

    float acc[8][NC];
#pragma unroll
    for (int i = 0; i < 4; i++)
#pragma unroll
        for (int j = 0; j < NC; j++) {
            unsigned lo, hi;
            UNPACK2(lo, hi, accP[i][j]);
            acc[2 * i][j]     = __uint_as_float(lo);
            acc[2 * i + 1][j] = __uint_as_float(hi);
        }

    if constexpr (!REPARAM) {
        float* O = Ob + (long)b * sO;
#pragma unroll
        for (int i = 0; i < 8; i++) {
            long r = rowTile + ry * 8 + i;
            float* orow = O + r * COUT + rx * NC;
            if constexpr (NC == 4) {
                float4 o;
                o.x = acc[i][0] + bb[0];
                o.y = acc[i][1] + bb[1];
                o.z = acc[i][2] + bb[2];
                o.w = acc[i][3] + bb[3];
                if (ACT == 1) {
                    o.x = fmaxf(o.x, 0.f); o.y = fmaxf(o.y, 0.f);
                    o.z = fmaxf(o.z, 0.f); o.w = fmaxf(o.w, 0.f);
                }
                *(float4*)orow = o;
            } else {
#pragma unroll
                for (int j = 0; j < NC; j++) {
                    float v = acc[i][j] + bb[j];
                    if (ACT == 1) v = fmaxf(v, 0.f);
                    orow[j] = v;
                }
            }
        }
    } else {
        // stage hl (+bias) into smem (reuse U: 128x64 floats), then reparam
        float* Hs = U;
        __syncthreads();    // all U reads done
#pragma unroll
        for (int i = 0; i < 8; i++) {
            float4 o;
            o.x = acc[i][0] + bb[0];
            o.y = acc[i][1] + bb[1];
            o.z = acc[i][2] + bb[2];
            o.w = acc[i][3] + bb[3];
            *(float4*)(Hs + (ry * 8 + i) * 64 + rx * 4) = o;
        }
        __syncthreads();
        int r = tid >> 1;
        int c0 = (tid & 1) * 16;
        long gr = (long)b * N2 + rowTile + r;
#pragma unroll
        for (int c = c0; c < c0 + 16; c += 4) {
            float4 m  = *(const float4*)(Hs + r * 64 + c);
            float4 lv = *(const float4*)(Hs + r * 64 + 32 + c);
            float4 e  = *(const float4*)(epsB + gr * LATENT + c);
            float4 z;
            z.x = m.x + expf(0.5f * lv.x) * e.x;
            z.y = m.y + expf(0.5f * lv.y) * e.y;
            z.z = m.z + expf(0.5f * lv.z) * e.z;
            z.w = m.w + expf(0.5f * lv.w) * e.w;
            *(float4*)(zB       + gr * LATENT + c) = z;
            *(float4*)(meanOutB + gr * LATENT + c) = m;
            *(float4*)(lvOutB   + gr * LATENT + c) = lv;
        }
    }
}

// ---------------- SpMM (single-hop ELL, batched) + fused pooling score --------
template<int C, int RPB>
__global__ void spmmT(const int2* __restrict__ edgeB, long eStride,
                      const int*  __restrict__ degB,  long dStride,
                      const float* __restrict__ Xb, long sX,
                      const float* __restrict__ bias,
                      float* __restrict__ Ob, long sO,
                      int act,
                      const float* __restrict__ p, float* __restrict__ yB)
{
    __shared__ float sp[C];
    __shared__ float sred[RPB][C / 32];

    int b = blockIdx.z;
    const float* X = Xb + (long)b * sX;
    float*       O = Ob + (long)b * sO;
    int tx = threadIdx.x, ty = threadIdx.y;
    int tid = ty * C + tx;
    int r = blockIdx.x * RPB + ty;

    if (p) {
        for (int t = tid; t < C; t += C * RPB) sp[t] = p[t];
        __syncthreads();
    }
    float bb = bias ? bias[tx] : 0.0f;

    pdl_wait();

    int deg = degB[(long)b * dStride + r];
    const int2* ep = edgeB + (long)b * eStride + (long)r * DEGMAX;
    float acc = 0.0f;
#pragma unroll 4
    for (int e = 0; e < deg; e++) {
        int2 pk = __ldg(ep + e);
        acc += __int_as_float(pk.y) * __ldg(X + (long)pk.x * C + tx);
    }
    acc += bb;
    if (act == 1)      acc = fmaxf(acc, 0.0f);
    else if (act == 2) acc = fmaxf(acc, 0.0f) + log1pf(expf(-fabsf(acc)));
    O[(long)r * C + tx] = acc;

    if (p) {
        float d = acc * sp[tx];
#pragma unroll
        for (int o = 16; o > 0; o >>= 1) d += __shfl_down_sync(0xffffffffu, d, o);
        if ((tx & 31) == 0) sred[ty][tx >> 5] = d;
        __syncthreads();
        if (tx == 0) {
            float s = 0.0f;
#pragma unroll
            for (int w = 0; w < C / 32; w++) s += sred[ty][w];
            yB[(long)b * N0 + r] = s;
        }
    }
}

// -------- descending crossing search over a histogram (warp 0) --------
__device__ __forceinline__ void crossing(const int* hist, int nbins, int kneed,
                                         int lane, int* sbin, int* sG)
{
    int per = nbins >> 5;
    int d0 = lane * per;
    int local = 0;
    for (int d = d0; d < d0 + per; d++) local += hist[nbins - 1 - d];
    int incl = local;
#pragma unroll
    for (int o = 1; o < 32; o <<= 1) {
        int v = __shfl_up_sync(0xffffffffu, incl, o);
        if (lane >= o) incl += v;
    }
    int excl = incl - local;
    if (excl < kneed && incl >= kneed) {
        int c = excl;
        for (int d = d0;; d++) {
            int hh = hist[nbins - 1 - d];
            if (c + hh >= kneed) { *sbin = nbins - 1 - d; *sG = c; break; }
            c += hh;
        }
    }
}

// -------- warp-shuffle block exclusive scan (1024 threads) --------
__device__ __forceinline__ int blockscan_excl(int v, int* swarp, int tid)
{
    int lane = tid & 31, w = tid >> 5;
    int incl = v;
#pragma unroll
    for (int o = 1; o < 32; o <<= 1) {
        int t = __shfl_up_sync(0xffffffffu, incl, o);
        if (lane >= o) incl += t;
    }
    __syncthreads();
    if (lane == 31) swarp[w] = incl;
    __syncthreads();
    if (w == 0) {
        int s = swarp[lane];
#pragma unroll
        for (int o = 1; o < 32; o <<= 1) {
            int t = __shfl_up_sync(0xffffffffu, s, o);
            if (lane >= o) s += t;
        }
        swarp[lane] = s;
    }
    __syncthreads();
    int base = w ? swarp[w - 1] : 0;
    return base + incl - v;
}

// -------- exact top-k: one histogram pass + boundary-bin exact rank (b = blockIdx.x) --
template<int IPT>
__global__ __launch_bounds__(1024)
void selectk_fast(const float* __restrict__ yB, int n, int k,
                  const float* __restrict__ p, int Cp,
                  const int* __restrict__ parentB, long sPar,
                  int* __restrict__ gidxB, int* __restrict__ lidxB,
                  float* __restrict__ gateB,
                  int* __restrict__ ginvB,
                  int* __restrict__ linvB, int linvLen)
{
    __shared__ unsigned su[4096];
    __shared__ int hist[2048];
    __shared__ unsigned char skeep[4096];
    __shared__ int glist[4096];
    __shared__ int swarp[32];
    __shared__ int s_bin, s_G, s_cnt;
    __shared__ float srn;

    int b = blockIdx.x, tid = threadIdx.x;
    const float* y = yB + (long)b * N0;

    if (tid < 32) {
        float s = 0.0f;
        for (int c = tid; c < Cp; c += 32) { float v = p[c]; s += v * v; }
#pragma unroll
        for (int o = 16; o > 0; o >>= 1) s += __shfl_down_sync(0xffffffffu, s, o);
        if (tid == 0) { srn = rsqrtf(s); s_cnt = 0; }
    }
    for (int i = tid; i < 2048; i += 1024) hist[i] = 0;

    pdl_wait();

    for (int i = tid; i < n; i += 1024) {
        unsigned s = __float_as_uint(y[i]);
        su[i] = (s & 0x80000000u) ? ~s : (s | 0x80000000u);
    }
    __syncthreads();
    for (int i = tid; i < n; i += 1024) atomicAdd(&hist[su[i] >> 21], 1);
    __syncthreads();
    if (tid < 32) crossing(hist, 2048, k, tid, &s_bin, &s_G);
    __syncthreads();
    unsigned b1 = (unsigned)s_bin;
    int need = k - s_G;

    for (int i = tid; i < n; i += 1024) {
        unsigned bin = su[i] >> 21;
        skeep[i] = (bin > b1);
        if (bin == b1) glist[atomicAdd(&s_cnt, 1)] = i;
    }
    __syncthreads();
    int cnt = s_cnt;
    for (int t = tid; t < cnt; t += 1024) {
        int i = glist[t];
        unsigned ui = su[i];
        int rk = 0;
        for (int j = 0; j < cnt; j++) {
            int jj = glist[j];
            unsigned uj = su[jj];
            rk += (uj > ui) || (uj == ui && jj < i);
        }
        if (rk < need) skeep[i] = 1;
    }
    __syncthreads();

    int i0 = tid * IPT;
    int keep[IPT];
    int ksum = 0;
#pragma unroll
    for (int t = 0; t < IPT; t++) { keep[t] = skeep[i0 + t]; ksum += keep[t]; }
    int base = blockscan_excl(ksum, swarp, tid);

    for (int i = tid; i < N0; i += 1024) ginvB[(long)b * N0 + i] = -1;
    if (linvB) for (int i = tid; i < linvLen; i += 1024) linvB[(long)b * linvLen + i] = -1;
    __syncthreads();

    float rn = srn;
    int pos = base;
#pragma unroll
    for (int t = 0; t < IPT; t++) {
        if (keep[t]) {
            int i = i0 + t;
            int g = parentB ? parentB[(long)b * sPar + i] : i;
            gidxB[(long)b * k + pos] = g;
            lidxB[(long)b * k + pos] = i;
            gateB[(long)b * k + pos] = tanhf(y[i] * rn);
            ginvB[(long)b * N0 + g] = pos;
            if (linvB) linvB[(long)b * linvLen + i] = pos;
            pos++;
        }
    }
}

// ---------------- launch ----------------
#define LAUNCH_PDL(kern, grid, block, smem, ...) do {                            \
    cudaLaunchConfig_t _cfg = {};                                                \
    _cfg.gridDim = (grid); _cfg.blockDim = (block);                              \
    _cfg.dynamicSmemBytes = (smem); _cfg.stream = 0;                             \
    cudaLaunchAttribute _at[1];                                                  \
    _at[0].id = cudaLaunchAttributeProgrammaticStreamSerialization;              \
    _at[0].val.programmaticStreamSerializationAllowed = 1;                       \
    _cfg.attrs = _at; _cfg.numAttrs = 1;                                         \
    cudaLaunchKernelEx(&_cfg, kern, __VA_ARGS__);                                \
} while (0)

extern "C" void kernel_launch(void* const* d_in, const int* in_sizes, int n_in,
                              void* d_out, int out_size)
{
    const float* x    = (const float*)d_in[0];
    const float* eps  = (const float*)d_in[1];
    const float* A0   = (const float*)d_in[2];
    const float* W1   = (const float*)d_in[3];
    const float* b1   = (const float*)d_in[4];
    const float* p1   = (const float*)d_in[5];
    const float* W2   = (const float*)d_in[6];
    const float* b2   = (const float*)d_in[7];
    const float* p2   = (const float*)d_in[8];
    const float* Wlat = (const float*)d_in[9];
    const float* blat = (const float*)d_in[10];
    const float* Wd0  = (const float*)d_in[11];
    const float* bd0  = (const float*)d_in[12];
    const float* Wd1  = (const float*)d_in[13];
    const float* bd1  = (const float*)d_in[14];
    const float* Wd2  = (const float*)d_in[15];
    const float* bd2  = (const float*)d_in[16];
    const float* Wout = (const float*)d_in[17];
    const float* bout = (const float*)d_in[18];

    float* out     = (float*)d_out;
    float* meanOut = out + (long)BATCH * N0 * FIN;
    float* lvOut   = meanOut + (long)BATCH * N2 * LATENT;

    float *xw, *h, *h1, *z, *d0, *y, *gate1, *gate2;
    int *gidx1, *ginv1, *gidx2, *lidx2, *ginv2, *linv2;
    int2 *edge0, *edge1, *edge01, *edge2a, *edge2, *edge12;
    int *deg0, *deg1, *deg01, *deg2a, *deg2, *deg12;
    cudaGetSymbolAddress((void**)&xw,    g_xw);
    cudaGetSymbolAddress((void**)&h,     g_h);
    cudaGetSymbolAddress((void**)&h1,    g_h1);
    cudaGetSymbolAddress((void**)&z,     g_z);
    cudaGetSymbolAddress((void**)&d0,    g_d0);
    cudaGetSymbolAddress((void**)&y,     g_y);
    cudaGetSymbolAddress((void**)&gidx1, g_gidx1);
    cudaGetSymbolAddress((void**)&ginv1, g_ginv1);
    cudaGetSymbolAddress((void**)&gate1, g_gate1);
    cudaGetSymbolAddress((void**)&gidx2, g_gidx2);
    cudaGetSymbolAddress((void**)&lidx2, g_lidx2);
    cudaGetSymbolAddress((void**)&ginv2, g_ginv2);
    cudaGetSymbolAddress((void**)&linv2, g_linv2);
    cudaGetSymbolAddress((void**)&gate2, g_gate2);
    cudaGetSymbolAddress((void**)&edge0, g_edge);
    cudaGetSymbolAddress((void**)&deg0,  g_deg);
    cudaGetSymbolAddress((void**)&edge1, g_edge1);
    cudaGetSymbolAddress((void**)&deg1,  g_deg1);
    cudaGetSymbolAddress((void**)&edge01, g_edge01);
    cudaGetSymbolAddress((void**)&deg01,  g_deg01);
    cudaGetSymbolAddress((void**)&edge2a, g_edge2a);
    cudaGetSymbolAddress((void**)&deg2a,  g_deg2a);
    cudaGetSymbolAddress((void**)&edge2,  g_edge2);
    cudaGetSymbolAddress((void**)&deg2,   g_deg2);
    cudaGetSymbolAddress((void**)&edge12, g_edge12);
    cudaGetSymbolAddress((void**)&deg12,  g_deg12);

    const long SXW = (long)N0 * 128;
    const long SH  = (long)N0 * 128;
    const long SH1 = (long)N1 * 96;
    const long SZ  = (long)N2 * LATENT;
    const long SD0 = (long)N2 * 64;
    const long E1S = (long)N1 * DEGMAX;
    const long E2S = (long)N2 * DEGMAX;
    const long E12S = (long)N1 * DEGMAX;
    const long E01S = (long)N0 * DEGMAX;

    const int SM_LAT  = (64 * 128 + 64 * 64) * 4;   // 49152
    const int SM_DEC0 = (32 * 128 + 32 * 64) * 4;   // 24576
    const int SM_DEC1 = (64 * 128 + 64 * 96) * 4;   // 57344
    cudaFuncSetAttribute((const void*)gcnF<64,64,0,1>,
                         cudaFuncAttributeMaxDynamicSharedMemorySize, SM_LAT);
    cudaFuncSetAttribute((const void*)gcnF<64,96,1,0>,
                         cudaFuncAttributeMaxDynamicSharedMemorySize, SM_DEC1);

    // 1. fused: sparsify A0 + t = A0@x (C=64) + zero y
    spmm0_build<<<N0, 256>>>(A0, x, xw, y);
    // 2. h = relu(t@W1 + b1), fused y = h.p1
    LAUNCH_PDL((gemmT<64,128,0,3>), dim3(2, N0/128, BATCH), dim3(256), 0,
        (const float*)xw, SXW, W1, b1, h, SH,
        (const int*)nullptr, (long)0, (const float*)nullptr, p1, y);

    // 3. pool1 selection
    LAUNCH_PDL((selectk_fast<4>), dim3(BATCH), dim3(1024), 0,
        (const float*)y, (int)N0, (int)N1, p1, (int)128,
        (const int*)nullptr, (long)0,
        gidx1, gidx1, gate1, ginv1, (int*)nullptr, (int)0);
    // 4. edge1 + edge01 builds
    LAUNCH_PDL(build_sub2, dim3(N1/8 + N0/8, BATCH), dim3(256), 0,
        (const int2*)edge0, (const int*)deg0,
        (const int*)gidx1, (const int*)ginv1,
        edge1, deg1, edge01, deg01);

    // 5. encoder GCN2 gemm + 6. spmm with fused pool2 score
    LAUNCH_PDL((gemmT<128,64,1,0>), dim3(1, N1/128, BATCH), dim3(256), 0,
        (const float*)h, SH, W2, (const float*)nullptr, xw, SXW,
        (const int*)gidx1, (long)N1, (const float*)gate1,
        (const float*)nullptr, (float*)nullptr);
    LAUNCH_PDL((spmmT<64,4>), dim3(N1/4, 1, BATCH), dim3(64, 4), 0,
        (const int2*)edge1, E1S, (const int*)deg1, (long)N1,
        (const float*)xw, SXW, b2, h1, SH1, (int)1, p2, y);

    // 7. pool2 selection
    LAUNCH_PDL((selectk_fast<2>), dim3(BATCH), dim3(1024), 0,
        (const float*)y, (int)N1, (int)N2, p2, (int)64,
        (const int*)gidx1, (long)N1,
        gidx2, lidx2, gate2, ginv2, linv2, (int)N1);
    // 8. edge2a + edge2 + edge12 builds
    LAUNCH_PDL(build2x, dim3(2*(N2/8) + N1/8, BATCH), dim3(256), 0,
        (const int2*)edge1, (const int*)deg1,
        (const int*)lidx2, (const int*)linv2, (const float*)gate2,
        edge2a, deg2a, edge2, deg2, edge12, deg12);

    // 9. latent fused GCN + reparam: z/mean/lv from A2@(gated h1)@Wlat + blat
    LAUNCH_PDL((gcnF<64,64,0,1>), dim3(1, N2/128, BATCH), dim3(256), SM_LAT,
        (const int2*)edge2a, E2S, (const int*)deg2a, (long)N2,
        (const float*)h1, SH1, Wlat, blat,
        (float*)nullptr, (long)0, eps, meanOut, lvOut, z);

    // 10. dec0 fused GCN: d0 = relu((A2@z)@Wd0 + bd0)
    LAUNCH_PDL((gcnF<32,64,1,0>), dim3(1, N2/128, BATCH), dim3(256), SM_DEC0,
        (const int2*)edge2, E2S, (const int*)deg2, (long)N2,
        (const float*)z, SZ, Wd0, bd0,
        d0, SD0, (const float*)nullptr, (float*)nullptr, (float*)nullptr, (float*)nullptr);

    // 11. dec1 fused GCN: h1 = relu((A1@unpool(d0))@Wd1 + bd1) via edge12
    LAUNCH_PDL((gcnF<64,96,1,0>), dim3(1, N1/128, BATCH), dim3(256), SM_DEC1,
        (const int2*)edge12, E12S, (const int*)deg12, (long)N1,
        (const float*)d0, SD0, Wd1, bd1,
        h1, SH1, (const float*)nullptr, (float*)nullptr, (float*)nullptr, (float*)nullptr);

    // 12. dec2 spmm: t = A0@unpool(h1) via pre-masked edge01 (C=96)
    LAUNCH_PDL((spmmT<96,2>), dim3(N0/2, 1, BATCH), dim3(96, 2), 0,
        (const int2*)edge01, E01S, (const int*)deg01, (long)N0,
        (const float*)h1, SH1, (const float*)nullptr, xw, SXW, (int)0,
        (const float*)nullptr, (float*)nullptr);
    // 13. dec2 gemm: h = relu(t@Wd2 + bd2)
    LAUNCH_PDL((gemmT<96,128,0,1>), dim3(2, N0/128, BATCH), dim3(256), 0,
        (const float*)xw, SXW, Wd2, bd2, h, SH,
        (const int*)nullptr, (long)0, (const float*)nullptr,
        (const float*)nullptr, (float*)nullptr);

    // 14. output gemm: t = h@Wout
    LAUNCH_PDL((gemmT<128,64,0,0>), dim3(1, N0/128, BATCH), dim3(256), 0,
        (const float*)h, SH, Wout, (const float*)nullptr, xw, SXW,
        (const int*)nullptr, (long)0, (const float*)nullptr,
        (const float*)nullptr, (float*)nullptr);
    // 15. output spmm + softplus
    LAUNCH_PDL((spmmT<64,4>), dim3(N0/4, 1, BATCH), dim3(64, 4), 0,
        (const int2*)edge0, (long)0, (const int*)deg0, (long)0,
        (const float*)xw, SXW, bout, out, (long)N0*FIN, (int)2,
        (const float*)nullptr, (float*)nullptr);
}

// round 14
// speedup vs baseline: 1.3691x; 1.3691x over previous
#include <cuda_runtime.h>
#include <math.h>

#define BATCH  8
#define N0     4096
#define N1     2048
#define N2     1024
#define FIN    64
#define LATENT 32
#define DEGMAX 128

// ---- packed fp32x2 helpers (Blackwell FFMA2 — only reachable via PTX) ----
#define PACK2(out, v) \
    asm("mov.b64 %0, {%1, %1};" : "=l"(out) : "r"(__float_as_uint(v)))
#define FMA2(acc, a, b) \
    asm("fma.rn.f32x2 %0, %1, %2, %0;" : "+l"(acc) : "l"(a), "l"(b))
#define UNPACK2(lo, hi, in) \
    asm("mov.b64 {%0, %1}, %2;" : "=r"(lo), "=r"(hi) : "l"(in))

// ---- PDL: wait until predecessor grid's memory is visible ----
__device__ __forceinline__ void pdl_wait() {
    asm volatile("griddepcontrol.wait;" ::: "memory");
}

// ---------------- device scratch ----------------
__device__ int   g_deg[N0];
__device__ int2  g_edge[N0 * DEGMAX];

__device__ int   g_deg1[BATCH * N1];
__device__ int2  g_edge1[BATCH * N1 * DEGMAX];
__device__ int   g_deg2[BATCH * N2];
__device__ int2  g_edge2[BATCH * N2 * DEGMAX];
__device__ int   g_deg01[BATCH * N0];
__device__ int2  g_edge01[BATCH * N0 * DEGMAX];

__device__ float g_xw[BATCH][N0 * 128];
__device__ float g_h [BATCH][N0 * 128];
__device__ float g_h1[BATCH][N1 * 96];
__device__ float g_hl[BATCH][N2 * 64];
__device__ float g_d0[BATCH][N2 * 64];
__device__ float g_y [BATCH][N0];

__device__ int   g_gidx1[BATCH][N1];
__device__ int   g_ginv1[BATCH][N0];
__device__ float g_gate1[BATCH][N1];
__device__ int   g_gidx2[BATCH][N2];
__device__ int   g_lidx2[BATCH][N2];
__device__ int   g_ginv2[BATCH][N0];
__device__ int   g_linv2[BATCH][N1];
__device__ float g_gate2[BATCH][N2];

// ---- fused: dense A0 row -> smem ELL (+persist) + spmm over x (all batches) + y zero ----
__global__ __launch_bounds__(256)
void spmm0_build(const float* __restrict__ A0, const float* __restrict__ x,
                 float* __restrict__ xwB, float* __restrict__ yB)
{
    __shared__ int2 sedge[DEGMAX];
    __shared__ int scnt[8];
    __shared__ int soff[8];
    __shared__ int sdeg;

    int r = blockIdx.x;
    int tid = threadIdx.x, w = tid >> 5, lane = tid & 31;
    const float* arow = A0 + (long)r * N0;

    int c0base = w * 512;
    int cnt = 0;
    for (int cc = c0base + lane; cc < c0base + 512; cc += 32) {
        unsigned m = __ballot_sync(0xffffffffu, arow[cc] != 0.0f);
        cnt += __popc(m);
    }
    if (lane == 0) scnt[w] = cnt;
    __syncthreads();
    if (tid == 0) {
        int s = 0;
        for (int i = 0; i < 8; i++) { soff[i] = s; s += scnt[i]; }
        sdeg = s < DEGMAX ? s : DEGMAX;
    }
    __syncthreads();

    int pos = soff[w];
    for (int cc = c0base + lane; cc < c0base + 512; cc += 32) {
        float v = arow[cc];
        unsigned m = __ballot_sync(0xffffffffu, v != 0.0f);
        if (v != 0.0f) {
            int p2 = pos + __popc(m & ((1u << lane) - 1u));
            if (p2 < DEGMAX) { int2 e; e.x = cc; e.y = __float_as_int(v); sedge[p2] = e; }
        }
        pos += __popc(m);
    }
    __syncthreads();

    int deg = sdeg;
    for (int e = tid; e < deg; e += 256) g_edge[(long)r * DEGMAX + e] = sedge[e];
    if (tid == 0) g_deg[r] = deg;
    if (tid < BATCH) yB[(long)tid * N0 + r] = 0.0f;

    int c = tid & 63, grp = tid >> 6;
    for (int b = grp; b < BATCH; b += 4) {
        const float* X = x + (long)b * N0 * FIN;
        float acc = 0.0f;
#pragma unroll 4
        for (int e = 0; e < deg; e++) {
            int2 pk = sedge[e];
            acc += __int_as_float(pk.y) * __ldg(X + (long)pk.x * FIN + c);
        }
        xwB[(long)b * ((long)N0 * 128) + (long)r * 64 + c] = acc;
    }
}

// ------- sub-ELL row remap core (one warp per row, ballot compaction) -------
__device__ __forceinline__ void build_row(int b, int r,
    const int2* __restrict__ srcEdge, long seStride,
    const int* __restrict__ srcDeg, long sdStride,
    const int* __restrict__ rowMapB, long sMap,
    const int* __restrict__ invB, long sInv,
    int2* __restrict__ dstEdge, int* __restrict__ dstDeg, int nrows)
{
    int lane = threadIdx.x & 31;
    int src = rowMapB ? rowMapB[(long)b * sMap + r] : r;
    const int2* ep = srcEdge + (long)b * seStride + (long)src * DEGMAX;
    int deg = srcDeg[(long)b * sdStride + src];
    const int* inv = invB + (long)b * sInv;
    int2* op = dstEdge + ((long)b * nrows + r) * DEGMAX;
    int base = 0;
    for (int c0 = 0; c0 < deg; c0 += 32) {
        int e = c0 + lane;
        int mc = -1; int2 pk;
        if (e < deg) { pk = __ldg(ep + e); mc = __ldg(inv + pk.x); }
        unsigned m = __ballot_sync(0xffffffffu, mc >= 0);
        if (mc >= 0) {
            int pos = base + __popc(m & ((1u << lane) - 1u));
            int2 o; o.x = mc; o.y = pk.y;
            op[pos] = o;
        }
        base += __popc(m);
    }
    if (lane == 0) dstDeg[(long)b * nrows + r] = base;
}

// ------- two-row variant: both rows' loads issued before either ballot (MLP x2) -----
__device__ __forceinline__ void build_row2(int b, int r0, int r1,
    const int2* __restrict__ srcEdge, long seStride,
    const int* __restrict__ srcDeg, long sdStride,
    const int* __restrict__ rowMapB, long sMap,
    const int* __restrict__ invB, long sInv,
    int2* __restrict__ dstEdge, int* __restrict__ dstDeg, int nrows)
{
    int lane = threadIdx.x & 31;
    int s0 = rowMapB ? rowMapB[(long)b * sMap + r0] : r0;
    int s1 = rowMapB ? rowMapB[(long)b * sMap + r1] : r1;
    const int2* ep0 = srcEdge + (long)b * seStride + (long)s0 * DEGMAX;
    const int2* ep1 = srcEdge + (long)b * seStride + (long)s1 * DEGMAX;
    int d0 = srcDeg[(long)b * sdStride + s0];
    int d1 = srcDeg[(long)b * sdStride + s1];
    const int* inv = invB + (long)b * sInv;
    int2* op0 = dstEdge + ((long)b * nrows + r0) * DEGMAX;
    int2* op1 = dstEdge + ((long)b * nrows + r1) * DEGMAX;
    int base0 = 0, base1 = 0;
    int dmax = d0 > d1 ? d0 : d1;
    for (int c0 = 0; c0 < dmax; c0 += 32) {
        int e = c0 + lane;
        int2 pk0, pk1;
        int mc0 = -1, mc1 = -1;
        // all loads issued before the first ballot consumes them
        if (e < d0) pk0 = __ldg(ep0 + e);
        if (e < d1) pk1 = __ldg(ep1 + e);
        if (e < d0) mc0 = __ldg(inv + pk0.x);
        if (e < d1) mc1 = __ldg(inv + pk1.x);
        unsigned m0 = __ballot_sync(0xffffffffu, mc0 >= 0);
        if (mc0 >= 0) {
            int pos = base0 + __popc(m0 & ((1u << lane) - 1u));
            int2 o; o.x = mc0; o.y = pk0.y;
            op0[pos] = o;
        }
        base0 += __popc(m0);
        unsigned m1 = __ballot_sync(0xffffffffu, mc1 >= 0);
        if (mc1 >= 0) {
            int pos = base1 + __popc(m1 & ((1u << lane) - 1u));
            int2 o; o.x = mc1; o.y = pk1.y;
            op1[pos] = o;
        }
        base1 += __popc(m1);
    }
    if (lane == 0) {
        dstDeg[(long)b * nrows + r0] = base0;
        dstDeg[(long)b * nrows + r1] = base1;
    }
}

// ------- sub-ELL build (batched: blockIdx.y = b) ----------
__global__ void build_sub(const int2* __restrict__ srcEdge, long seStride,
                          const int* __restrict__ srcDeg, long sdStride,
                          const int* __restrict__ rowMapB, long sMap,
                          const int* __restrict__ invB, long sInv,
                          int2* __restrict__ dstEdge, int* __restrict__ dstDeg,
                          int nrows)
{
    pdl_wait();
    int b = blockIdx.y;
    int r = blockIdx.x * (blockDim.x >> 5) + (threadIdx.x >> 5);
    if (r >= nrows) return;
    build_row(b, r, srcEdge, seStride, srcDeg, sdStride, rowMapB, sMap,
              invB, sInv, dstEdge, dstDeg, nrows);
}

// ------- dual sub-ELL build after pool1: edge1 + edge01, 2 rows per warp ----
__global__ void build_sub2(const int2* __restrict__ edge0, const int* __restrict__ deg0,
                           const int* __restrict__ gidx1, const int* __restrict__ ginv1,
                           int2* __restrict__ edge1, int* __restrict__ deg1,
                           int2* __restrict__ edge01, int* __restrict__ deg01)
{
    pdl_wait();
    int b = blockIdx.y;
    int bx = blockIdx.x;
    int w = threadIdx.x >> 5;
    if (bx < N1 / 16) {
        int r0 = (bx * 8 + w) * 2;
        build_row2(b, r0, r0 + 1, edge0, 0, deg0, 0, gidx1, N1, ginv1, N0,
                   edge1, deg1, N1);
    } else {
        int r0 = ((bx - N1 / 16) * 8 + w) * 2;
        build_row2(b, r0, r0 + 1, edge0, 0, deg0, 0, nullptr, 0, ginv1, N0,
                   edge01, deg01, N0);
    }
}

// ---------------- GEMM: 128x64 tile, 8x4 per thread, FFMA2 (batched) ----------
// MODE 0: plain  MODE 1: gather*scale  MODE 2: inv (-1 -> zero)  MODE 3: reparam
// EPI bit0: bias+relu ; bit1: fused y += relu_row . p
template<int K, int C, int MODE, int EPI>
__global__ __launch_bounds__(256)
void gemmT(const float* __restrict__ Ab, long sA,
           const float* __restrict__ W,
           const float* __restrict__ bias,
           float* __restrict__ Ob, long sO,
           const int* __restrict__ mapB, long sMap,
           const float* __restrict__ scaleB,
           const float* __restrict__ p, float* __restrict__ yB,
           const float* __restrict__ epsB,
           float* __restrict__ meanOutB, float* __restrict__ lvOutB)
{
    __shared__ float As[32][128];
    __shared__ float Ws[32][64];

    int b = blockIdx.z;
    const float* A = Ab + (long)b * sA;
    float*       O = Ob + (long)b * sO;
    int tid = threadIdx.x;
    int rowTile = blockIdx.y * 128;
    int colTile = blockIdx.x * 64;

    int lr = tid >> 1;
    int lk = (tid & 1) * 16;
    int grow = rowTile + lr;
    int wr  = tid >> 3;
    int wc0 = (tid & 7) * 8;
    int ry = tid >> 4, rx = tid & 15;

    // pre-wait prologue: W is a read-only kernel input — preload k-tile 0
#pragma unroll
    for (int t = 0; t < 8; t += 4) {
        int cc = colTile + wc0 + t;
        float4 v = (cc < C) ? *(const float4*)(W + (long)wr * C + cc)
                            : make_float4(0.f, 0.f, 0.f, 0.f);
        *(float4*)&Ws[wr][wc0 + t] = v;
    }

    pdl_wait();

    const float* asrc = nullptr;
    float ascale = 1.0f;
    if (MODE == 0) {
        asrc = A + (long)grow * K;
    } else if (MODE == 1) {
        int s = mapB[(long)b * sMap + grow];
        asrc = A + (long)s * K;
        ascale = scaleB[(long)b * sMap + grow];
    } else if (MODE == 2) {
        int s = mapB[(long)b * sMap + grow];
        asrc = (s >= 0) ? (A + (long)s * K) : nullptr;
    }

    unsigned long long accP[4][4];
#pragma unroll
    for (int i = 0; i < 4; i++)
#pragma unroll
        for (int j = 0; j < 4; j++) accP[i][j] = 0ull;

    for (int kt = 0; kt < K; kt += 32) {
        if (MODE == 3) {
#pragma unroll
            for (int t = 0; t < 16; t += 4) {
                float4 m  = *(const float4*)(A + (long)grow * 64 + lk + t);
                float4 lv = *(const float4*)(A + (long)grow * 64 + 32 + lk + t);
                float4 e  = *(const float4*)(epsB + ((long)b * N2 + grow) * LATENT + lk + t);
                float4 z;
                z.x = m.x + expf(0.5f * lv.x) * e.x;
                z.y = m.y + expf(0.5f * lv.y) * e.y;
                z.z = m.z + expf(0.5f * lv.z) * e.z;
                z.w = m.w + expf(0.5f * lv.w) * e.w;
                As[lk + t + 0][lr] = z.x;
                As[lk + t + 1][lr] = z.y;
                As[lk + t + 2][lr] = z.z;
                As[lk + t + 3][lr] = z.w;
                *(float4*)(meanOutB + ((long)b * N2 + grow) * LATENT + lk + t) = m;
                *(float4*)(lvOutB   + ((long)b * N2 + grow) * LATENT + lk + t) = lv;
            }
        } else {
#pragma unroll
            for (int t = 0; t < 16; t += 4) {
                float4 v = asrc ? *(const float4*)(asrc + kt + lk + t)
                                : make_float4(0.f, 0.f, 0.f, 0.f);
                As[lk + t + 0][lr] = v.x * ascale;
                As[lk + t + 1][lr] = v.y * ascale;
                As[lk + t + 2][lr] = v.z * ascale;
                As[lk + t + 3][lr] = v.w * ascale;
            }
        }
        if (kt > 0) {
#pragma unroll
            for (int t = 0; t < 8; t += 4) {
                int cc = colTile + wc0 + t;
                float4 v = (cc < C) ? *(const float4*)(W + (long)(kt + wr) * C + cc)
                                    : make_float4(0.f, 0.f, 0.f, 0.f);
                *(float4*)&Ws[wr][wc0 + t] = v;
            }
        }
        __syncthreads();

#pragma unroll
        for (int kk = 0; kk < 32; kk++) {
            ulonglong2 a01 = *(const ulonglong2*)(&As[kk][ry * 8]);
            ulonglong2 a23 = *(const ulonglong2*)(&As[kk][ry * 8 + 4]);
            float4 wv = *(const float4*)(&Ws[kk][rx * 4]);
            unsigned long long w0, w1, w2, w3;
            PACK2(w0, wv.x); PACK2(w1, wv.y); PACK2(w2, wv.z); PACK2(w3, wv.w);

            FMA2(accP[0][0], a01.x, w0); FMA2(accP[0][1], a01.x, w1);
            FMA2(accP[0][2], a01.x, w2); FMA2(accP[0][3], a01.x, w3);
            FMA2(accP[1][0], a01.y, w0); FMA2(accP[1][1], a01.y, w1);
            FMA2(accP[1][2], a01.y, w2); FMA2(accP[1][3], a01.y, w3);
            FMA2(accP[2][0], a23.x, w0); FMA2(accP[2][1], a23.x, w1);
            FMA2(accP[2][2], a23.x, w2); FMA2(accP[2][3], a23.x, w3);
            FMA2(accP[3][0], a23.y, w0); FMA2(accP[3][1], a23.y, w1);
            FMA2(accP[3][2], a23.y, w2); FMA2(accP[3][3], a23.y, w3);
        }
        __syncthreads();
    }

    float acc[8][4];
#pragma unroll
    for (int i = 0; i < 4; i++)
#pragma unroll
        for (int j = 0; j < 4; j++) {
            unsigned lo, hi;
            UNPACK2(lo, hi, accP[i][j]);
            acc[2 * i][j]     = __uint_as_float(lo);
            acc[2 * i + 1][j] = __uint_as_float(hi);
        }

    int cc = colTile + rx * 4;
    if (cc < C) {
        if (EPI == 0) {
#pragma unroll
            for (int i = 0; i < 8; i++) {
                long r = rowTile + ry * 8 + i;
                *(float4*)(O + r * C + cc) =
                    make_float4(acc[i][0], acc[i][1], acc[i][2], acc[i][3]);
            }
        } else {
            float4 bv = *(const float4*)(bias + cc);
            float4 pv = make_float4(0.f, 0.f, 0.f, 0.f);
            if (EPI & 2) pv = *(const float4*)(p + cc);
            float part[8];
#pragma unroll
            for (int i = 0; i < 8; i++) {
                long r = rowTile + ry * 8 + i;
                float4 o;
                o.x = fmaxf(acc[i][0] + bv.x, 0.0f);
                o.y = fmaxf(acc[i][1] + bv.y, 0.0f);
                o.z = fmaxf(acc[i][2] + bv.z, 0.0f);
                o.w = fmaxf(acc[i][3] + bv.w, 0.0f);
                *(float4*)(O + r * C + cc) = o;
                part[i] = o.x * pv.x + o.y * pv.y + o.z * pv.z + o.w * pv.w;
            }
            if (EPI & 2) {
#pragma unroll
                for (int i = 0; i < 8; i++) {
                    float v = part[i];
#pragma unroll
                    for (int o = 8; o > 0; o >>= 1)
                        v += __shfl_down_sync(0xffffffffu, v, o, 16);
                    if ((tid & 15) == 0)
                        atomicAdd(&yB[(long)b * N0 + rowTile + ry * 8 + i], v);
                }
            }
        }
    }
}

// ---------------- SpMM (single-hop ELL, batched) + fused pooling score --------
template<int C, int RPB>
__global__ void spmmT(const int2* __restrict__ edgeB, long eStride,
                      const int*  __restrict__ degB,  long dStride,
                      const float* __restrict__ Xb, long sX,
                      const float* __restrict__ bias,
                      float* __restrict__ Ob, long sO,
                      int act,
                      const float* __restrict__ p, float* __restrict__ yB)
{
    __shared__ float sp[C];
    __shared__ float sred[RPB][C / 32];

    int b = blockIdx.z;
    const float* X = Xb + (long)b * sX;
    float*       O = Ob + (long)b * sO;
    int tx = threadIdx.x, ty = threadIdx.y;
    int tid = ty * C + tx;
    int r = blockIdx.x * RPB + ty;

    if (p) {
        for (int t = tid; t < C; t += C * RPB) sp[t] = p[t];
        __syncthreads();
    }
    float bb = bias ? bias[tx] : 0.0f;

    pdl_wait();

    int deg = degB[(long)b * dStride + r];
    const int2* ep = edgeB + (long)b * eStride + (long)r * DEGMAX;
    float acc = 0.0f;
#pragma unroll 4
    for (int e = 0; e < deg; e++) {
        int2 pk = __ldg(ep + e);
        acc += __int_as_float(pk.y) * __ldg(X + (long)pk.x * C + tx);
    }
    acc += bb;
    if (act == 1)      acc = fmaxf(acc, 0.0f);
    else if (act == 2) acc = fmaxf(acc, 0.0f) + log1pf(expf(-fabsf(acc)));
    O[(long)r * C + tx] = acc;

    if (p) {
        float d = acc * sp[tx];
#pragma unroll
        for (int o = 16; o > 0; o >>= 1) d += __shfl_down_sync(0xffffffffu, d, o);
        if ((tx & 31) == 0) sred[ty][tx >> 5] = d;
        __syncthreads();
        if (tx == 0) {
            float s = 0.0f;
#pragma unroll
            for (int w = 0; w < C / 32; w++) s += sred[ty][w];
            yB[(long)b * N0 + r] = s;
        }
    }
}

// -------- descending crossing search over a histogram (warp 0) --------
__device__ __forceinline__ void crossing(const int* hist, int nbins, int kneed,
                                         int lane, int* sbin, int* sG)
{
    int per = nbins >> 5;
    int d0 = lane * per;
    int local = 0;
    for (int d = d0; d < d0 + per; d++) local += hist[nbins - 1 - d];
    int incl = local;
#pragma unroll
    for (int o = 1; o < 32; o <<= 1) {
        int v = __shfl_up_sync(0xffffffffu, incl, o);
        if (lane >= o) incl += v;
    }
    int excl = incl - local;
    if (excl < kneed && incl >= kneed) {
        int c = excl;
        for (int d = d0;; d++) {
            int hh = hist[nbins - 1 - d];
            if (c + hh >= kneed) { *sbin = nbins - 1 - d; *sG = c; break; }
            c += hh;
        }
    }
}

// -------- warp-shuffle block exclusive scan (1024 threads) --------
__device__ __forceinline__ int blockscan_excl(int v, int* swarp, int tid)
{
    int lane = tid & 31, w = tid >> 5;
    int incl = v;
#pragma unroll
    for (int o = 1; o < 32; o <<= 1) {
        int t = __shfl_up_sync(0xffffffffu, incl, o);
        if (lane >= o) incl += t;
    }
    __syncthreads();
    if (lane == 31) swarp[w] = incl;
    __syncthreads();
    if (w == 0) {
        int s = swarp[lane];
#pragma unroll
        for (int o = 1; o < 32; o <<= 1) {
            int t = __shfl_up_sync(0xffffffffu, s, o);
            if (lane >= o) s += t;
        }
        swarp[lane] = s;
    }
    __syncthreads();
    int base = w ? swarp[w - 1] : 0;
    return base + incl - v;
}

// -------- exact top-k: one histogram pass + boundary-bin exact rank (b = blockIdx.x) --
template<int IPT>
__global__ __launch_bounds__(1024)
void selectk_fast(const float* __restrict__ yB, int n, int k,
                  const float* __restrict__ p, int Cp,
                  const int* __restrict__ parentB, long sPar,
                  int* __restrict__ gidxB, int* __restrict__ lidxB,
                  float* __restrict__ gateB,
                  int* __restrict__ ginvB,
                  int* __restrict__ linvB, int linvLen)
{
    __shared__ unsigned su[4096];
    __shared__ int hist[2048];
    __shared__ unsigned char skeep[4096];
    __shared__ int glist[4096];
    __shared__ int swarp[32];
    __shared__ int s_bin, s_G, s_cnt;
    __shared__ float srn;

    int b = blockIdx.x, tid = threadIdx.x;
    const float* y = yB + (long)b * N0;

    if (tid < 32) {
        float s = 0.0f;
        for (int c = tid; c < Cp; c += 32) { float v = p[c]; s += v * v; }
#pragma unroll
        for (int o = 16; o > 0; o >>= 1) s += __shfl_down_sync(0xffffffffu, s, o);
        if (tid == 0) { srn = rsqrtf(s); s_cnt = 0; }
    }
    for (int i = tid; i < 2048; i += 1024) hist[i] = 0;

    pdl_wait();

    for (int i = tid; i < n; i += 1024) {
        unsigned s = __float_as_uint(y[i]);
        su[i] = (s & 0x80000000u) ? ~s : (s | 0x80000000u);
    }
    __syncthreads();
    for (int i = tid; i < n; i += 1024) atomicAdd(&hist[su[i] >> 21], 1);
    __syncthreads();
    if (tid < 32) crossing(hist, 2048, k, tid, &s_bin, &s_G);
    __syncthreads();
    unsigned b1 = (unsigned)s_bin;
    int need = k - s_G;

    for (int i = tid; i < n; i += 1024) {
        unsigned bin = su[i] >> 21;
        skeep[i] = (bin > b1);
        if (bin == b1) glist[atomicAdd(&s_cnt, 1)] = i;
    }
    __syncthreads();
    int cnt = s_cnt;
    for (int t = tid; t < cnt; t += 1024) {
        int i = glist[t];
        unsigned ui = su[i];
        int rk = 0;
        for (int j = 0; j < cnt; j++) {
            int jj = glist[j];
            unsigned uj = su[jj];
            rk += (uj > ui) || (uj == ui && jj < i);
        }
        if (rk < need) skeep[i] = 1;
    }
    __syncthreads();

    int i0 = tid * IPT;
    int keep[IPT];
    int ksum = 0;
#pragma unroll
    for (int t = 0; t < IPT; t++) { keep[t] = skeep[i0 + t]; ksum += keep[t]; }
    int base = blockscan_excl(ksum, swarp, tid);

    for (int i = tid; i < N0; i += 1024) ginvB[(long)b * N0 + i] = -1;
    if (linvB) for (int i = tid; i < linvLen; i += 1024) linvB[(long)b * linvLen + i] = -1;
    __syncthreads();

    float rn = srn;
    int pos = base;
#pragma unroll
    for (int t = 0; t < IPT; t++) {
        if (keep[t]) {
            int i = i0 + t;
            int g = parentB ? parentB[(long)b * sPar + i] : i;
            gidxB[(long)b * k + pos] = g;
            lidxB[(long)b * k + pos] = i;
            gateB[(long)b * k + pos] = tanhf(y[i] * rn);
            ginvB[(long)b * N0 + g] = pos;
            if (linvB) linvB[(long)b * linvLen + i] = pos;
            pos++;
        }
    }
}

// ---------------- launch ----------------
#define LAUNCH_PDL(kern, grid, block, ...) do {                                  \
    cudaLaunchConfig_t _cfg = {};                                                \
    _cfg.gridDim = (grid); _cfg.blockDim = (block);                              \
    _cfg.dynamicSmemBytes = 0; _cfg.stream = 0;                                  \
    cudaLaunchAttribute _at[1];                                                  \
    _at[0].id = cudaLaunchAttributeProgrammaticStreamSerialization;              \
    _at[0].val.programmaticStreamSerializationAllowed = 1;                       \
    _cfg.attrs = _at; _cfg.numAttrs = 1;                                         \
    cudaLaunchKernelEx(&_cfg, kern, __VA_ARGS__);                                \
} while (0)

extern "C" void kernel_launch(void* const* d_in, const int* in_sizes, int n_in,
                              void* d_out, int out_size)
{
    const float* x    = (const float*)d_in[0];
    const float* eps  = (const float*)d_in[1];
    const float* A0   = (const float*)d_in[2];
    const float* W1   = (const float*)d_in[3];
    const float* b1   = (const float*)d_in[4];
    const float* p1   = (const float*)d_in[5];
    const float* W2   = (const float*)d_in[6];
    const float* b2   = (const float*)d_in[7];
    const float* p2   = (const float*)d_in[8];
    const float* Wlat = (const float*)d_in[9];
    const float* blat = (const float*)d_in[10];
    const float* Wd0  = (const float*)d_in[11];
    const float* bd0  = (const float*)d_in[12];
    const float* Wd1  = (const float*)d_in[13];
    const float* bd1  = (const float*)d_in[14];
    const float* Wd2  = (const float*)d_in[15];
    const float* bd2  = (const float*)d_in[16];
    const float* Wout = (const float*)d_in[17];
    const float* bout = (const float*)d_in[18];

    float* out     = (float*)d_out;
    float* meanOut = out + (long)BATCH * N0 * FIN;
    float* lvOut   = meanOut + (long)BATCH * N2 * LATENT;

    float *xw, *h, *h1, *hl, *d0, *y, *gate1, *gate2;
    int *gidx1, *ginv1, *gidx2, *lidx2, *ginv2, *linv2;
    int2 *edge0, *edge1, *edge2, *edge01;
    int *deg0, *deg1, *deg2, *deg01;
    cudaGetSymbolAddress((void**)&xw,    g_xw);
    cudaGetSymbolAddress((void**)&h,     g_h);
    cudaGetSymbolAddress((void**)&h1,    g_h1);
    cudaGetSymbolAddress((void**)&hl,    g_hl);
    cudaGetSymbolAddress((void**)&d0,    g_d0);
    cudaGetSymbolAddress((void**)&y,     g_y);
    cudaGetSymbolAddress((void**)&gidx1, g_gidx1);
    cudaGetSymbolAddress((void**)&ginv1, g_ginv1);
    cudaGetSymbolAddress((void**)&gate1, g_gate1);
    cudaGetSymbolAddress((void**)&gidx2, g_gidx2);
    cudaGetSymbolAddress((void**)&lidx2, g_lidx2);
    cudaGetSymbolAddress((void**)&ginv2, g_ginv2);
    cudaGetSymbolAddress((void**)&linv2, g_linv2);
    cudaGetSymbolAddress((void**)&gate2, g_gate2);
    cudaGetSymbolAddress((void**)&edge0, g_edge);
    cudaGetSymbolAddress((void**)&deg0,  g_deg);
    cudaGetSymbolAddress((void**)&edge1, g_edge1);
    cudaGetSymbolAddress((void**)&deg1,  g_deg1);
    cudaGetSymbolAddress((void**)&edge2, g_edge2);
    cudaGetSymbolAddress((void**)&deg2,  g_deg2);
    cudaGetSymbolAddress((void**)&edge01, g_edge01);
    cudaGetSymbolAddress((void**)&deg01,  g_deg01);

    const long SXW = (long)N0 * 128;
    const long SH  = (long)N0 * 128;
    const long SH1 = (long)N1 * 96;
    const long SHL = (long)N2 * 64;
    const long SD0 = (long)N2 * 64;
    const long E1S = (long)N1 * DEGMAX;
    const long E2S = (long)N2 * DEGMAX;
    const long E01S = (long)N0 * DEGMAX;

    // 1. fused: sparsify A0 + t = A0@x (C=64) + zero y
    spmm0_build<<<N0, 256>>>(A0, x, xw, y);
    // h = relu(t@W1 + b1), fused y = h.p1
    LAUNCH_PDL((gemmT<64,128,0,3>), dim3(2, N0/128, BATCH), dim3(256),
        (const float*)xw, SXW, W1, b1, h, SH,
        (const int*)nullptr, (long)0, (const float*)nullptr, p1, y,
        (const float*)nullptr, (float*)nullptr, (float*)nullptr);

    // 2. pool1 selection + both level1 sub-adjacency builds (2 rows/warp)
    LAUNCH_PDL((selectk_fast<4>), dim3(BATCH), dim3(1024),
        (const float*)y, (int)N0, (int)N1, p1, (int)128,
        (const int*)nullptr, (long)0,
        gidx1, gidx1, gate1, ginv1, (int*)nullptr, (int)0);
    LAUNCH_PDL(build_sub2, dim3(N1/16 + N0/16, BATCH), dim3(256),
        (const int2*)edge0, (const int*)deg0,
        (const int*)gidx1, (const int*)ginv1,
        edge1, deg1, edge01, deg01);

    // 3. encoder GCN2 + fused pool2 score
    LAUNCH_PDL((gemmT<128,64,1,0>), dim3(1, N1/128, BATCH), dim3(256),
        (const float*)h, SH, W2, (const float*)nullptr, xw, SXW,
        (const int*)gidx1, (long)N1, (const float*)gate1,
        (const float*)nullptr, (float*)nullptr,
        (const float*)nullptr, (float*)nullptr, (float*)nullptr);
    LAUNCH_PDL((spmmT<64,4>), dim3(N1/4, 1, BATCH), dim3(64, 4),
        (const int2*)edge1, E1S, (const int*)deg1, (long)N1,
        (const float*)xw, SXW, b2, h1, SH1, (int)1, p2, y);

    // 4. pool2 selection + level2 build
    LAUNCH_PDL((selectk_fast<2>), dim3(BATCH), dim3(1024),
        (const float*)y, (int)N1, (int)N2, p2, (int)64,
        (const int*)gidx1, (long)N1,
        gidx2, lidx2, gate2, ginv2, linv2, (int)N1);
    LAUNCH_PDL(build_sub, dim3(N2/8, BATCH), dim3(256),
        (const int2*)edge1, E1S, (const int*)deg1, (long)N1,
        (const int*)lidx2, (long)N2, (const int*)linv2, (long)N1,
        edge2, deg2, (int)N2);

    // 5. latent GCN
    LAUNCH_PDL((gemmT<64,64,1,0>), dim3(1, N2/128, BATCH), dim3(256),
        (const float*)h1, SH1, Wlat, (const float*)nullptr, xw, SXW,
        (const int*)lidx2, (long)N2, (const float*)gate2,
        (const float*)nullptr, (float*)nullptr,
        (const float*)nullptr, (float*)nullptr, (float*)nullptr);
    LAUNCH_PDL((spmmT<64,4>), dim3(N2/4, 1, BATCH), dim3(64, 4),
        (const int2*)edge2, E2S, (const int*)deg2, (long)N2,
        (const float*)xw, SXW, blat, hl, SHL, (int)0,
        (const float*)nullptr, (float*)nullptr);

    // 6+7. decoder GCN0 with fused reparameterization
    LAUNCH_PDL((gemmT<32,64,3,0>), dim3(1, N2/128, BATCH), dim3(256),
        (const float*)hl, SHL, Wd0, (const float*)nullptr, xw, SXW,
        (const int*)nullptr, (long)0, (const float*)nullptr,
        (const float*)nullptr, (float*)nullptr, eps, meanOut, lvOut);
    LAUNCH_PDL((spmmT<64,4>), dim3(N2/4, 1, BATCH), dim3(64, 4),
        (const int2*)edge2, E2S, (const int*)deg2, (long)N2,
        (const float*)xw, SXW, bd0, d0, SD0, (int)1,
        (const float*)nullptr, (float*)nullptr);

    // 8. unpool->level1, decoder GCN1
    LAUNCH_PDL((gemmT<64,96,2,0>), dim3(2, N1/128, BATCH), dim3(256),
        (const float*)d0, SD0, Wd1, (const float*)nullptr, xw, SXW,
        (const int*)linv2, (long)N1, (const float*)nullptr,
        (const float*)nullptr, (float*)nullptr,
        (const float*)nullptr, (float*)nullptr, (float*)nullptr);
    LAUNCH_PDL((spmmT<96,2>), dim3(N1/2, 1, BATCH), dim3(96, 2),
        (const int2*)edge1, E1S, (const int*)deg1, (long)N1,
        (const float*)xw, SXW, bd1, h1, SH1, (int)1,
        (const float*)nullptr, (float*)nullptr);

    // 9. decoder GCN2 swapped: t = A0@unpool(h1) via pre-masked edge01
    LAUNCH_PDL((spmmT<96,2>), dim3(N0/2, 1, BATCH), dim3(96, 2),
        (const int2*)edge01, E01S, (const int*)deg01, (long)N0,
        (const float*)h1, SH1, (const float*)nullptr, xw, SXW, (int)0,
        (const float*)nullptr, (float*)nullptr);
    LAUNCH_PDL((gemmT<96,128,0,1>), dim3(2, N0/128, BATCH), dim3(256),
        (const float*)xw, SXW, Wd2, bd2, h, SH,
        (const int*)nullptr, (long)0, (const float*)nullptr,
        (const float*)nullptr, (float*)nullptr,
        (const float*)nullptr, (float*)nullptr, (float*)nullptr);

    // 10. output GCN + softplus
    LAUNCH_PDL((gemmT<128,64,0,0>), dim3(1, N0/128, BATCH), dim3(256),
        (const float*)h, SH, Wout, (const float*)nullptr, xw, SXW,
        (const int*)nullptr, (long)0, (const float*)nullptr,
        (const float*)nullptr, (float*)nullptr,
        (const float*)nullptr, (float*)nullptr, (float*)nullptr);
    LAUNCH_PDL((spmmT<64,4>), dim3(N0/4, 1, BATCH), dim3(64, 4),
        (const int2*)edge0, (long)0, (const int*)deg0, (long)0,
        (const float*)xw, SXW, bout, out, (long)N0*FIN, (int)2,
        (const float*)nullptr, (float*)nullptr);
}

// round 15
// speedup vs baseline: 1.4073x; 1.0279x over previous
#include <cuda_runtime.h>
#include <math.h>

#define BATCH  8
#define N0     4096
#define N1     2048
#define N2     1024
#define FIN    64
#define LATENT 32
#define DEGMAX 128

// ---- packed fp32x2 helpers (Blackwell FFMA2 — only reachable via PTX) ----
#define PACK2(out, v) \
    asm("mov.b64 %0, {%1, %1};" : "=l"(out) : "r"(__float_as_uint(v)))
#define FMA2(acc, a, b) \
    asm("fma.rn.f32x2 %0, %1, %2, %0;" : "+l"(acc) : "l"(a), "l"(b))
#define UNPACK2(lo, hi, in) \
    asm("mov.b64 {%0, %1}, %2;" : "=r"(lo), "=r"(hi) : "l"(in))

// ---- PDL: wait until predecessor grid's memory is visible ----
__device__ __forceinline__ void pdl_wait() {
    asm volatile("griddepcontrol.wait;" ::: "memory");
}

// ---------------- device scratch ----------------
__device__ int   g_deg[N0];
__device__ int2  g_edge[N0 * DEGMAX];

__device__ int   g_deg1[BATCH * N1];
__device__ int2  g_edge1[BATCH * N1 * DEGMAX];
__device__ int   g_deg2[BATCH * N2];
__device__ int2  g_edge2[BATCH * N2 * DEGMAX];
__device__ int   g_deg01[BATCH * N0];
__device__ int2  g_edge01[BATCH * N0 * DEGMAX];

__device__ float g_xw[BATCH][N0 * 128];
__device__ float g_h [BATCH][N0 * 128];
__device__ float g_h1[BATCH][N1 * 96];
__device__ float g_hl[BATCH][N2 * 64];
__device__ float g_d0[BATCH][N2 * 64];
__device__ float g_y [BATCH][N0];

__device__ int   g_gidx1[BATCH][N1];
__device__ int   g_ginv1[BATCH][N0];
__device__ float g_gate1[BATCH][N1];
__device__ int   g_gidx2[BATCH][N2];
__device__ int   g_lidx2[BATCH][N2];
__device__ int   g_ginv2[BATCH][N0];
__device__ int   g_linv2[BATCH][N1];
__device__ float g_gate2[BATCH][N2];

// ---- fused: dense A0 row -> smem ELL (+persist) + spmm over x (all batches) + y zero ----
// phase B: each thread accumulates TWO batches per edge pass (1 smem read -> 2 X loads,
// 2 independent FMA chains) instead of two sequential passes.
__global__ __launch_bounds__(256)
void spmm0_build(const float* __restrict__ A0, const float* __restrict__ x,
                 float* __restrict__ xwB, float* __restrict__ yB)
{
    __shared__ int2 sedge[DEGMAX];
    __shared__ int scnt[8];
    __shared__ int soff[8];
    __shared__ int sdeg;

    int r = blockIdx.x;
    int tid = threadIdx.x, w = tid >> 5, lane = tid & 31;
    const float* arow = A0 + (long)r * N0;

    int c0base = w * 512;
    int cnt = 0;
    for (int cc = c0base + lane; cc < c0base + 512; cc += 32) {
        unsigned m = __ballot_sync(0xffffffffu, arow[cc] != 0.0f);
        cnt += __popc(m);
    }
    if (lane == 0) scnt[w] = cnt;
    __syncthreads();
    if (tid == 0) {
        int s = 0;
        for (int i = 0; i < 8; i++) { soff[i] = s; s += scnt[i]; }
        sdeg = s < DEGMAX ? s : DEGMAX;
    }
    __syncthreads();

    int pos = soff[w];
    for (int cc = c0base + lane; cc < c0base + 512; cc += 32) {
        float v = arow[cc];
        unsigned m = __ballot_sync(0xffffffffu, v != 0.0f);
        if (v != 0.0f) {
            int p2 = pos + __popc(m & ((1u << lane) - 1u));
            if (p2 < DEGMAX) { int2 e; e.x = cc; e.y = __float_as_int(v); sedge[p2] = e; }
        }
        pos += __popc(m);
    }
    __syncthreads();

    int deg = sdeg;
    for (int e = tid; e < deg; e += 256) g_edge[(long)r * DEGMAX + e] = sedge[e];
    if (tid == 0) g_deg[r] = deg;
    if (tid < BATCH) yB[(long)tid * N0 + r] = 0.0f;

    // phase B: thread handles batches grp and grp+4 in ONE edge pass
    int c = tid & 63, grp = tid >> 6;
    {
        const float* X0 = x + (long)grp * N0 * FIN + c;
        const float* X1 = x + (long)(grp + 4) * N0 * FIN + c;
        float a0 = 0.0f, a1 = 0.0f;
#pragma unroll 4
        for (int e = 0; e < deg; e++) {
            int2 pk = sedge[e];
            float v = __int_as_float(pk.y);
            long off = (long)pk.x * FIN;
            float x0 = __ldg(X0 + off);
            float x1 = __ldg(X1 + off);
            a0 += v * x0;
            a1 += v * x1;
        }
        long rbase = (long)r * 64 + c;
        xwB[(long)grp       * ((long)N0 * 128) + rbase] = a0;
        xwB[(long)(grp + 4) * ((long)N0 * 128) + rbase] = a1;
    }
}

// ------- sub-ELL row remap core (one warp per row, ballot compaction) -------
__device__ __forceinline__ void build_row(int b, int r,
    const int2* __restrict__ srcEdge, long seStride,
    const int* __restrict__ srcDeg, long sdStride,
    const int* __restrict__ rowMapB, long sMap,
    const int* __restrict__ invB, long sInv,
    int2* __restrict__ dstEdge, int* __restrict__ dstDeg, int nrows)
{
    int lane = threadIdx.x & 31;
    int src = rowMapB ? rowMapB[(long)b * sMap + r] : r;
    const int2* ep = srcEdge + (long)b * seStride + (long)src * DEGMAX;
    int deg = srcDeg[(long)b * sdStride + src];
    const int* inv = invB + (long)b * sInv;
    int2* op = dstEdge + ((long)b * nrows + r) * DEGMAX;
    int base = 0;
    for (int c0 = 0; c0 < deg; c0 += 32) {
        int e = c0 + lane;
        int mc = -1; int2 pk;
        if (e < deg) { pk = __ldg(ep + e); mc = __ldg(inv + pk.x); }
        unsigned m = __ballot_sync(0xffffffffu, mc >= 0);
        if (mc >= 0) {
            int pos = base + __popc(m & ((1u << lane) - 1u));
            int2 o; o.x = mc; o.y = pk.y;
            op[pos] = o;
        }
        base += __popc(m);
    }
    if (lane == 0) dstDeg[(long)b * nrows + r] = base;
}

// ------- two-row variant: both rows' loads issued before either ballot (MLP x2) -----
__device__ __forceinline__ void build_row2(int b, int r0, int r1,
    const int2* __restrict__ srcEdge, long seStride,
    const int* __restrict__ srcDeg, long sdStride,
    const int* __restrict__ rowMapB, long sMap,
    const int* __restrict__ invB, long sInv,
    int2* __restrict__ dstEdge, int* __restrict__ dstDeg, int nrows)
{
    int lane = threadIdx.x & 31;
    int s0 = rowMapB ? rowMapB[(long)b * sMap + r0] : r0;
    int s1 = rowMapB ? rowMapB[(long)b * sMap + r1] : r1;
    const int2* ep0 = srcEdge + (long)b * seStride + (long)s0 * DEGMAX;
    const int2* ep1 = srcEdge + (long)b * seStride + (long)s1 * DEGMAX;
    int d0 = srcDeg[(long)b * sdStride + s0];
    int d1 = srcDeg[(long)b * sdStride + s1];
    const int* inv = invB + (long)b * sInv;
    int2* op0 = dstEdge + ((long)b * nrows + r0) * DEGMAX;
    int2* op1 = dstEdge + ((long)b * nrows + r1) * DEGMAX;
    int base0 = 0, base1 = 0;
    int dmax = d0 > d1 ? d0 : d1;
    for (int c0 = 0; c0 < dmax; c0 += 32) {
        int e = c0 + lane;
        int2 pk0, pk1;
        int mc0 = -1, mc1 = -1;
        if (e < d0) pk0 = __ldg(ep0 + e);
        if (e < d1) pk1 = __ldg(ep1 + e);
        if (e < d0) mc0 = __ldg(inv + pk0.x);
        if (e < d1) mc1 = __ldg(inv + pk1.x);
        unsigned m0 = __ballot_sync(0xffffffffu, mc0 >= 0);
        if (mc0 >= 0) {
            int pos = base0 + __popc(m0 & ((1u << lane) - 1u));
            int2 o; o.x = mc0; o.y = pk0.y;
            op0[pos] = o;
        }
        base0 += __popc(m0);
        unsigned m1 = __ballot_sync(0xffffffffu, mc1 >= 0);
        if (mc1 >= 0) {
            int pos = base1 + __popc(m1 & ((1u << lane) - 1u));
            int2 o; o.x = mc1; o.y = pk1.y;
            op1[pos] = o;
        }
        base1 += __popc(m1);
    }
    if (lane == 0) {
        dstDeg[(long)b * nrows + r0] = base0;
        dstDeg[(long)b * nrows + r1] = base1;
    }
}

// ------- sub-ELL build (batched: blockIdx.y = b) ----------
__global__ void build_sub(const int2* __restrict__ srcEdge, long seStride,
                          const int* __restrict__ srcDeg, long sdStride,
                          const int* __restrict__ rowMapB, long sMap,
                          const int* __restrict__ invB, long sInv,
                          int2* __restrict__ dstEdge, int* __restrict__ dstDeg,
                          int nrows)
{
    pdl_wait();
    int b = blockIdx.y;
    int r = blockIdx.x * (blockDim.x >> 5) + (threadIdx.x >> 5);
    if (r >= nrows) return;
    build_row(b, r, srcEdge, seStride, srcDeg, sdStride, rowMapB, sMap,
              invB, sInv, dstEdge, dstDeg, nrows);
}

// ------- dual sub-ELL build after pool1: edge1 + edge01, 2 rows per warp ----
__global__ void build_sub2(const int2* __restrict__ edge0, const int* __restrict__ deg0,
                           const int* __restrict__ gidx1, const int* __restrict__ ginv1,
                           int2* __restrict__ edge1, int* __restrict__ deg1,
                           int2* __restrict__ edge01, int* __restrict__ deg01)
{
    pdl_wait();
    int b = blockIdx.y;
    int bx = blockIdx.x;
    int w = threadIdx.x >> 5;
    if (bx < N1 / 16) {
        int r0 = (bx * 8 + w) * 2;
        build_row2(b, r0, r0 + 1, edge0, 0, deg0, 0, gidx1, N1, ginv1, N0,
                   edge1, deg1, N1);
    } else {
        int r0 = ((bx - N1 / 16) * 8 + w) * 2;
        build_row2(b, r0, r0 + 1, edge0, 0, deg0, 0, nullptr, 0, ginv1, N0,
                   edge01, deg01, N0);
    }
}

// ---------------- GEMM: 128x64 tile, 8x4 per thread, FFMA2 (batched) ----------
// MODE 0: plain  MODE 1: gather*scale  MODE 2: inv (-1 -> zero)  MODE 3: reparam
// EPI bit0: bias+relu ; bit1: fused y += relu_row . p
template<int K, int C, int MODE, int EPI>
__global__ __launch_bounds__(256)
void gemmT(const float* __restrict__ Ab, long sA,
           const float* __restrict__ W,
           const float* __restrict__ bias,
           float* __restrict__ Ob, long sO,
           const int* __restrict__ mapB, long sMap,
           const float* __restrict__ scaleB,
           const float* __restrict__ p, float* __restrict__ yB,
           const float* __restrict__ epsB,
           float* __restrict__ meanOutB, float* __restrict__ lvOutB)
{
    __shared__ float As[32][128];
    __shared__ float Ws[32][64];

    int b = blockIdx.z;
    const float* A = Ab + (long)b * sA;
    float*       O = Ob + (long)b * sO;
    int tid = threadIdx.x;
    int rowTile = blockIdx.y * 128;
    int colTile = blockIdx.x * 64;

    int lr = tid >> 1;
    int lk = (tid & 1) * 16;
    int grow = rowTile + lr;
    int wr  = tid >> 3;
    int wc0 = (tid & 7) * 8;
    int ry = tid >> 4, rx = tid & 15;

    // pre-wait prologue: W is a read-only kernel input — preload k-tile 0
#pragma unroll
    for (int t = 0; t < 8; t += 4) {
        int cc = colTile + wc0 + t;
        float4 v = (cc < C) ? *(const float4*)(W + (long)wr * C + cc)
                            : make_float4(0.f, 0.f, 0.f, 0.f);
        *(float4*)&Ws[wr][wc0 + t] = v;
    }

    pdl_wait();

    const float* asrc = nullptr;
    float ascale = 1.0f;
    if (MODE == 0) {
        asrc = A + (long)grow * K;
    } else if (MODE == 1) {
        int s = mapB[(long)b * sMap + grow];
        asrc = A + (long)s * K;
        ascale = scaleB[(long)b * sMap + grow];
    } else if (MODE == 2) {
        int s = mapB[(long)b * sMap + grow];
        asrc = (s >= 0) ? (A + (long)s * K) : nullptr;
    }

    unsigned long long accP[4][4];
#pragma unroll
    for (int i = 0; i < 4; i++)
#pragma unroll
        for (int j = 0; j < 4; j++) accP[i][j] = 0ull;

    for (int kt = 0; kt < K; kt += 32) {
        if (MODE == 3) {
#pragma unroll
            for (int t = 0; t < 16; t += 4) {
                float4 m  = *(const float4*)(A + (long)grow * 64 + lk + t);
                float4 lv = *(const float4*)(A + (long)grow * 64 + 32 + lk + t);
                float4 e  = *(const float4*)(epsB + ((long)b * N2 + grow) * LATENT + lk + t);
                float4 z;
                z.x = m.x + expf(0.5f * lv.x) * e.x;
                z.y = m.y + expf(0.5f * lv.y) * e.y;
                z.z = m.z + expf(0.5f * lv.z) * e.z;
                z.w = m.w + expf(0.5f * lv.w) * e.w;
                As[lk + t + 0][lr] = z.x;
                As[lk + t + 1][lr] = z.y;
                As[lk + t + 2][lr] = z.z;
                As[lk + t + 3][lr] = z.w;
                *(float4*)(meanOutB + ((long)b * N2 + grow) * LATENT + lk + t) = m;
                *(float4*)(lvOutB   + ((long)b * N2 + grow) * LATENT + lk + t) = lv;
            }
        } else {
#pragma unroll
            for (int t = 0; t < 16; t += 4) {
                float4 v = asrc ? *(const float4*)(asrc + kt + lk + t)
                                : make_float4(0.f, 0.f, 0.f, 0.f);
                As[lk + t + 0][lr] = v.x * ascale;
                As[lk + t + 1][lr] = v.y * ascale;
                As[lk + t + 2][lr] = v.z * ascale;
                As[lk + t + 3][lr] = v.w * ascale;
            }
        }
        if (kt > 0) {
#pragma unroll
            for (int t = 0; t < 8; t += 4) {
                int cc = colTile + wc0 + t;
                float4 v = (cc < C) ? *(const float4*)(W + (long)(kt + wr) * C + cc)
                                    : make_float4(0.f, 0.f, 0.f, 0.f);
                *(float4*)&Ws[wr][wc0 + t] = v;
            }
        }
        __syncthreads();

#pragma unroll
        for (int kk = 0; kk < 32; kk++) {
            ulonglong2 a01 = *(const ulonglong2*)(&As[kk][ry * 8]);
            ulonglong2 a23 = *(const ulonglong2*)(&As[kk][ry * 8 + 4]);
            float4 wv = *(const float4*)(&Ws[kk][rx * 4]);
            unsigned long long w0, w1, w2, w3;
            PACK2(w0, wv.x); PACK2(w1, wv.y); PACK2(w2, wv.z); PACK2(w3, wv.w);

            FMA2(accP[0][0], a01.x, w0); FMA2(accP[0][1], a01.x, w1);
            FMA2(accP[0][2], a01.x, w2); FMA2(accP[0][3], a01.x, w3);
            FMA2(accP[1][0], a01.y, w0); FMA2(accP[1][1], a01.y, w1);
            FMA2(accP[1][2], a01.y, w2); FMA2(accP[1][3], a01.y, w3);
            FMA2(accP[2][0], a23.x, w0); FMA2(accP[2][1], a23.x, w1);
            FMA2(accP[2][2], a23.x, w2); FMA2(accP[2][3], a23.x, w3);
            FMA2(accP[3][0], a23.y, w0); FMA2(accP[3][1], a23.y, w1);
            FMA2(accP[3][2], a23.y, w2); FMA2(accP[3][3], a23.y, w3);
        }
        __syncthreads();
    }

    float acc[8][4];
#pragma unroll
    for (int i = 0; i < 4; i++)
#pragma unroll
        for (int j = 0; j < 4; j++) {
            unsigned lo, hi;
            UNPACK2(lo, hi, accP[i][j]);
            acc[2 * i][j]     = __uint_as_float(lo);
            acc[2 * i + 1][j] = __uint_as_float(hi);
        }

    int cc = colTile + rx * 4;
    if (cc < C) {
        if (EPI == 0) {
#pragma unroll
            for (int i = 0; i < 8; i++) {
                long r = rowTile + ry * 8 + i;
                *(float4*)(O + r * C + cc) =
                    make_float4(acc[i][0], acc[i][1], acc[i][2], acc[i][3]);
            }
        } else {
            float4 bv = *(const float4*)(bias + cc);
            float4 pv = make_float4(0.f, 0.f, 0.f, 0.f);
            if (EPI & 2) pv = *(const float4*)(p + cc);
            float part[8];
#pragma unroll
            for (int i = 0; i < 8; i++) {
                long r = rowTile + ry * 8 + i;
                float4 o;
                o.x = fmaxf(acc[i][0] + bv.x, 0.0f);
                o.y = fmaxf(acc[i][1] + bv.y, 0.0f);
                o.z = fmaxf(acc[i][2] + bv.z, 0.0f);
                o.w = fmaxf(acc[i][3] + bv.w, 0.0f);
                *(float4*)(O + r * C + cc) = o;
                part[i] = o.x * pv.x + o.y * pv.y + o.z * pv.z + o.w * pv.w;
            }
            if (EPI & 2) {
#pragma unroll
                for (int i = 0; i < 8; i++) {
                    float v = part[i];
#pragma unroll
                    for (int o = 8; o > 0; o >>= 1)
                        v += __shfl_down_sync(0xffffffffu, v, o, 16);
                    if ((tid & 15) == 0)
                        atomicAdd(&yB[(long)b * N0 + rowTile + ry * 8 + i], v);
                }
            }
        }
    }
}

// ---------------- SpMM (single-hop ELL, batched) + fused pooling score --------
template<int C, int RPB>
__global__ void spmmT(const int2* __restrict__ edgeB, long eStride,
                      const int*  __restrict__ degB,  long dStride,
                      const float* __restrict__ Xb, long sX,
                      const float* __restrict__ bias,
                      float* __restrict__ Ob, long sO,
                      int act,
                      const float* __restrict__ p, float* __restrict__ yB)
{
    __shared__ float sp[C];
    __shared__ float sred[RPB][C / 32];

    int b = blockIdx.z;
    const float* X = Xb + (long)b * sX;
    float*       O = Ob + (long)b * sO;
    int tx = threadIdx.x, ty = threadIdx.y;
    int tid = ty * C + tx;
    int r = blockIdx.x * RPB + ty;

    if (p) {
        for (int t = tid; t < C; t += C * RPB) sp[t] = p[t];
        __syncthreads();
    }
    float bb = bias ? bias[tx] : 0.0f;

    pdl_wait();

    int deg = degB[(long)b * dStride + r];
    const int2* ep = edgeB + (long)b * eStride + (long)r * DEGMAX;
    float acc = 0.0f;
#pragma unroll 4
    for (int e = 0; e < deg; e++) {
        int2 pk = __ldg(ep + e);
        acc += __int_as_float(pk.y) * __ldg(X + (long)pk.x * C + tx);
    }
    acc += bb;
    if (act == 1)      acc = fmaxf(acc, 0.0f);
    else if (act == 2) acc = fmaxf(acc, 0.0f) + log1pf(expf(-fabsf(acc)));
    O[(long)r * C + tx] = acc;

    if (p) {
        float d = acc * sp[tx];
#pragma unroll
        for (int o = 16; o > 0; o >>= 1) d += __shfl_down_sync(0xffffffffu, d, o);
        if ((tx & 31) == 0) sred[ty][tx >> 5] = d;
        __syncthreads();
        if (tx == 0) {
            float s = 0.0f;
#pragma unroll
            for (int w = 0; w < C / 32; w++) s += sred[ty][w];
            yB[(long)b * N0 + r] = s;
        }
    }
}

// -------- descending crossing search over a histogram (warp 0) --------
__device__ __forceinline__ void crossing(const int* hist, int nbins, int kneed,
                                         int lane, int* sbin, int* sG)
{
    int per = nbins >> 5;
    int d0 = lane * per;
    int local = 0;
    for (int d = d0; d < d0 + per; d++) local += hist[nbins - 1 - d];
    int incl = local;
#pragma unroll
    for (int o = 1; o < 32; o <<= 1) {
        int v = __shfl_up_sync(0xffffffffu, incl, o);
        if (lane >= o) incl += v;
    }
    int excl = incl - local;
    if (excl < kneed && incl >= kneed) {
        int c = excl;
        for (int d = d0;; d++) {
            int hh = hist[nbins - 1 - d];
            if (c + hh >= kneed) { *sbin = nbins - 1 - d; *sG = c; break; }
            c += hh;
        }
    }
}

// -------- warp-shuffle block exclusive scan (1024 threads) --------
__device__ __forceinline__ int blockscan_excl(int v, int* swarp, int tid)
{
    int lane = tid & 31, w = tid >> 5;
    int incl = v;
#pragma unroll
    for (int o = 1; o < 32; o <<= 1) {
        int t = __shfl_up_sync(0xffffffffu, incl, o);
        if (lane >= o) incl += t;
    }
    __syncthreads();
    if (lane == 31) swarp[w] = incl;
    __syncthreads();
    if (w == 0) {
        int s = swarp[lane];
#pragma unroll
        for (int o = 1; o < 32; o <<= 1) {
            int t = __shfl_up_sync(0xffffffffu, s, o);
            if (lane >= o) s += t;
        }
        swarp[lane] = s;
    }
    __syncthreads();
    int base = w ? swarp[w - 1] : 0;
    return base + incl - v;
}

// -------- exact top-k: one histogram pass + boundary-bin exact rank (b = blockIdx.x) --
template<int IPT>
__global__ __launch_bounds__(1024)
void selectk_fast(const float* __restrict__ yB, int n, int k,
                  const float* __restrict__ p, int Cp,
                  const int* __restrict__ parentB, long sPar,
                  int* __restrict__ gidxB, int* __restrict__ lidxB,
                  float* __restrict__ gateB,
                  int* __restrict__ ginvB,
                  int* __restrict__ linvB, int linvLen)
{
    __shared__ unsigned su[4096];
    __shared__ int hist[2048];
    __shared__ unsigned char skeep[4096];
    __shared__ int glist[4096];
    __shared__ int swarp[32];
    __shared__ int s_bin, s_G, s_cnt;
    __shared__ float srn;

    int b = blockIdx.x, tid = threadIdx.x;
    const float* y = yB + (long)b * N0;

    if (tid < 32) {
        float s = 0.0f;
        for (int c = tid; c < Cp; c += 32) { float v = p[c]; s += v * v; }
#pragma unroll
        for (int o = 16; o > 0; o >>= 1) s += __shfl_down_sync(0xffffffffu, s, o);
        if (tid == 0) { srn = rsqrtf(s); s_cnt = 0; }
    }
    for (int i = tid; i < 2048; i += 1024) hist[i] = 0;

    pdl_wait();

    for (int i = tid; i < n; i += 1024) {
        unsigned s = __float_as_uint(y[i]);
        su[i] = (s & 0x80000000u) ? ~s : (s | 0x80000000u);
    }
    __syncthreads();
    for (int i = tid; i < n; i += 1024) atomicAdd(&hist[su[i] >> 21], 1);
    __syncthreads();
    if (tid < 32) crossing(hist, 2048, k, tid, &s_bin, &s_G);
    __syncthreads();
    unsigned b1 = (unsigned)s_bin;
    int need = k - s_G;

    for (int i = tid; i < n; i += 1024) {
        unsigned bin = su[i] >> 21;
        skeep[i] = (bin > b1);
        if (bin == b1) glist[atomicAdd(&s_cnt, 1)] = i;
    }
    __syncthreads();
    int cnt = s_cnt;
    for (int t = tid; t < cnt; t += 1024) {
        int i = glist[t];
        unsigned ui = su[i];
        int rk = 0;
        for (int j = 0; j < cnt; j++) {
            int jj = glist[j];
            unsigned uj = su[jj];
            rk += (uj > ui) || (uj == ui && jj < i);
        }
        if (rk < need) skeep[i] = 1;
    }
    __syncthreads();

    int i0 = tid * IPT;
    int keep[IPT];
    int ksum = 0;
#pragma unroll
    for (int t = 0; t < IPT; t++) { keep[t] = skeep[i0 + t]; ksum += keep[t]; }
    int base = blockscan_excl(ksum, swarp, tid);

    for (int i = tid; i < N0; i += 1024) ginvB[(long)b * N0 + i] = -1;
    if (linvB) for (int i = tid; i < linvLen; i += 1024) linvB[(long)b * linvLen + i] = -1;
    __syncthreads();

    float rn = srn;
    int pos = base;
#pragma unroll
    for (int t = 0; t < IPT; t++) {
        if (keep[t]) {
            int i = i0 + t;
            int g = parentB ? parentB[(long)b * sPar + i] : i;
            gidxB[(long)b * k + pos] = g;
            lidxB[(long)b * k + pos] = i;
            gateB[(long)b * k + pos] = tanhf(y[i] * rn);
            ginvB[(long)b * N0 + g] = pos;
            if (linvB) linvB[(long)b * linvLen + i] = pos;
            pos++;
        }
    }
}

// ---------------- launch ----------------
#define LAUNCH_PDL(kern, grid, block, ...) do {                                  \
    cudaLaunchConfig_t _cfg = {};                                                \
    _cfg.gridDim = (grid); _cfg.blockDim = (block);                              \
    _cfg.dynamicSmemBytes = 0; _cfg.stream = 0;                                  \
    cudaLaunchAttribute _at[1];                                                  \
    _at[0].id = cudaLaunchAttributeProgrammaticStreamSerialization;              \
    _at[0].val.programmaticStreamSerializationAllowed = 1;                       \
    _cfg.attrs = _at; _cfg.numAttrs = 1;                                         \
    cudaLaunchKernelEx(&_cfg, kern, __VA_ARGS__);                                \
} while (0)

extern "C" void kernel_launch(void* const* d_in, const int* in_sizes, int n_in,
                              void* d_out, int out_size)
{
    const float* x    = (const float*)d_in[0];
    const float* eps  = (const float*)d_in[1];
    const float* A0   = (const float*)d_in[2];
    const float* W1   = (const float*)d_in[3];
    const float* b1   = (const float*)d_in[4];
    const float* p1   = (const float*)d_in[5];
    const float* W2   = (const float*)d_in[6];
    const float* b2   = (const float*)d_in[7];
    const float* p2   = (const float*)d_in[8];
    const float* Wlat = (const float*)d_in[9];
    const float* blat = (const float*)d_in[10];
    const float* Wd0  = (const float*)d_in[11];
    const float* bd0  = (const float*)d_in[12];
    const float* Wd1  = (const float*)d_in[13];
    const float* bd1  = (const float*)d_in[14];
    const float* Wd2  = (const float*)d_in[15];
    const float* bd2  = (const float*)d_in[16];
    const float* Wout = (const float*)d_in[17];
    const float* bout = (const float*)d_in[18];

    float* out     = (float*)d_out;
    float* meanOut = out + (long)BATCH * N0 * FIN;
    float* lvOut   = meanOut + (long)BATCH * N2 * LATENT;

    float *xw, *h, *h1, *hl, *d0, *y, *gate1, *gate2;
    int *gidx1, *ginv1, *gidx2, *lidx2, *ginv2, *linv2;
    int2 *edge0, *edge1, *edge2, *edge01;
    int *deg0, *deg1, *deg2, *deg01;
    cudaGetSymbolAddress((void**)&xw,    g_xw);
    cudaGetSymbolAddress((void**)&h,     g_h);
    cudaGetSymbolAddress((void**)&h1,    g_h1);
    cudaGetSymbolAddress((void**)&hl,    g_hl);
    cudaGetSymbolAddress((void**)&d0,    g_d0);
    cudaGetSymbolAddress((void**)&y,     g_y);
    cudaGetSymbolAddress((void**)&gidx1, g_gidx1);
    cudaGetSymbolAddress((void**)&ginv1, g_ginv1);
    cudaGetSymbolAddress((void**)&gate1, g_gate1);
    cudaGetSymbolAddress((void**)&gidx2, g_gidx2);
    cudaGetSymbolAddress((void**)&lidx2, g_lidx2);
    cudaGetSymbolAddress((void**)&ginv2, g_ginv2);
    cudaGetSymbolAddress((void**)&linv2, g_linv2);
    cudaGetSymbolAddress((void**)&gate2, g_gate2);
    cudaGetSymbolAddress((void**)&edge0, g_edge);
    cudaGetSymbolAddress((void**)&deg0,  g_deg);
    cudaGetSymbolAddress((void**)&edge1, g_edge1);
    cudaGetSymbolAddress((void**)&deg1,  g_deg1);
    cudaGetSymbolAddress((void**)&edge2, g_edge2);
    cudaGetSymbolAddress((void**)&deg2,  g_deg2);
    cudaGetSymbolAddress((void**)&edge01, g_edge01);
    cudaGetSymbolAddress((void**)&deg01,  g_deg01);

    const long SXW = (long)N0 * 128;
    const long SH  = (long)N0 * 128;
    const long SH1 = (long)N1 * 96;
    const long SHL = (long)N2 * 64;
    const long SD0 = (long)N2 * 64;
    const long E1S = (long)N1 * DEGMAX;
    const long E2S = (long)N2 * DEGMAX;
    const long E01S = (long)N0 * DEGMAX;

    // 1. fused: sparsify A0 + t = A0@x (C=64, dual-batch ILP) + zero y
    spmm0_build<<<N0, 256>>>(A0, x, xw, y);
    // h = relu(t@W1 + b1), fused y = h.p1
    LAUNCH_PDL((gemmT<64,128,0,3>), dim3(2, N0/128, BATCH), dim3(256),
        (const float*)xw, SXW, W1, b1, h, SH,
        (const int*)nullptr, (long)0, (const float*)nullptr, p1, y,
        (const float*)nullptr, (float*)nullptr, (float*)nullptr);

    // 2. pool1 selection + both level1 sub-adjacency builds (2 rows/warp)
    LAUNCH_PDL((selectk_fast<4>), dim3(BATCH), dim3(1024),
        (const float*)y, (int)N0, (int)N1, p1, (int)128,
        (const int*)nullptr, (long)0,
        gidx1, gidx1, gate1, ginv1, (int*)nullptr, (int)0);
    LAUNCH_PDL(build_sub2, dim3(N1/16 + N0/16, BATCH), dim3(256),
        (const int2*)edge0, (const int*)deg0,
        (const int*)gidx1, (const int*)ginv1,
        edge1, deg1, edge01, deg01);

    // 3. encoder GCN2 + fused pool2 score
    LAUNCH_PDL((gemmT<128,64,1,0>), dim3(1, N1/128, BATCH), dim3(256),
        (const float*)h, SH, W2, (const float*)nullptr, xw, SXW,
        (const int*)gidx1, (long)N1, (const float*)gate1,
        (const float*)nullptr, (float*)nullptr,
        (const float*)nullptr, (float*)nullptr, (float*)nullptr);
    LAUNCH_PDL((spmmT<64,4>), dim3(N1/4, 1, BATCH), dim3(64, 4),
        (const int2*)edge1, E1S, (const int*)deg1, (long)N1,
        (const float*)xw, SXW, b2, h1, SH1, (int)1, p2, y);

    // 4. pool2 selection + level2 build
    LAUNCH_PDL((selectk_fast<2>), dim3(BATCH), dim3(1024),
        (const float*)y, (int)N1, (int)N2, p2, (int)64,
        (const int*)gidx1, (long)N1,
        gidx2, lidx2, gate2, ginv2, linv2, (int)N1);
    LAUNCH_PDL(build_sub, dim3(N2/8, BATCH), dim3(256),
        (const int2*)edge1, E1S, (const int*)deg1, (long)N1,
        (const int*)lidx2, (long)N2, (const int*)linv2, (long)N1,
        edge2, deg2, (int)N2);

    // 5. latent GCN
    LAUNCH_PDL((gemmT<64,64,1,0>), dim3(1, N2/128, BATCH), dim3(256),
        (const float*)h1, SH1, Wlat, (const float*)nullptr, xw, SXW,
        (const int*)lidx2, (long)N2, (const float*)gate2,
        (const float*)nullptr, (float*)nullptr,
        (const float*)nullptr, (float*)nullptr, (float*)nullptr);
    LAUNCH_PDL((spmmT<64,4>), dim3(N2/4, 1, BATCH), dim3(64, 4),
        (const int2*)edge2, E2S, (const int*)deg2, (long)N2,
        (const float*)xw, SXW, blat, hl, SHL, (int)0,
        (const float*)nullptr, (float*)nullptr);

    // 6+7. decoder GCN0 with fused reparameterization
    LAUNCH_PDL((gemmT<32,64,3,0>), dim3(1, N2/128, BATCH), dim3(256),
        (const float*)hl, SHL, Wd0, (const float*)nullptr, xw, SXW,
        (const int*)nullptr, (long)0, (const float*)nullptr,
        (const float*)nullptr, (float*)nullptr, eps, meanOut, lvOut);
    LAUNCH_PDL((spmmT<64,4>), dim3(N2/4, 1, BATCH), dim3(64, 4),
        (const int2*)edge2, E2S, (const int*)deg2, (long)N2,
        (const float*)xw, SXW, bd0, d0, SD0, (int)1,
        (const float*)nullptr, (float*)nullptr);

    // 8. unpool->level1, decoder GCN1
    LAUNCH_PDL((gemmT<64,96,2,0>), dim3(2, N1/128, BATCH), dim3(256),
        (const float*)d0, SD0, Wd1, (const float*)nullptr, xw, SXW,
        (const int*)linv2, (long)N1, (const float*)nullptr,
        (const float*)nullptr, (float*)nullptr,
        (const float*)nullptr, (float*)nullptr, (float*)nullptr);
    LAUNCH_PDL((spmmT<96,2>), dim3(N1/2, 1, BATCH), dim3(96, 2),
        (const int2*)edge1, E1S, (const int*)deg1, (long)N1,
        (const float*)xw, SXW, bd1, h1, SH1, (int)1,
        (const float*)nullptr, (float*)nullptr);

    // 9. decoder GCN2 swapped: t = A0@unpool(h1) via pre-masked edge01
    LAUNCH_PDL((spmmT<96,2>), dim3(N0/2, 1, BATCH), dim3(96, 2),
        (const int2*)edge01, E01S, (const int*)deg01, (long)N0,
        (const float*)h1, SH1, (const float*)nullptr, xw, SXW, (int)0,
        (const float*)nullptr, (float*)nullptr);
    LAUNCH_PDL((gemmT<96,128,0,1>), dim3(2, N0/128, BATCH), dim3(256),
        (const float*)xw, SXW, Wd2, bd2, h, SH,
        (const int*)nullptr, (long)0, (const float*)nullptr,
        (const float*)nullptr, (float*)nullptr,
        (const float*)nullptr, (float*)nullptr, (float*)nullptr);

    // 10. output GCN + softplus
    LAUNCH_PDL((gemmT<128,64,0,0>), dim3(1, N0/128, BATCH), dim3(256),
        (const float*)h, SH, Wout, (const float*)nullptr, xw, SXW,
        (const int*)nullptr, (long)0, (const float*)nullptr,
        (const float*)nullptr, (float*)nullptr,
        (const float*)nullptr, (float*)nullptr, (float*)nullptr);
    LAUNCH_PDL((spmmT<64,4>), dim3(N0/4, 1, BATCH), dim3(64, 4),
        (const int2*)edge0, (long)0, (const int*)deg0, (long)0,
        (const float*)xw, SXW, bout, out, (long)N0*FIN, (int)2,
        (const float*)nullptr, (float*)nullptr);
}